// round 3
// baseline (speedup 1.0000x reference)
#include <cuda_runtime.h>
#include <cuda_bf16.h>

#define NNODES 20000
#define NEDGES 320000
#define FEA    16
#define FOUT   256
#define EPSV   1e-5f

// ---------------- scratch (static __device__ — no allocation allowed) -------
__device__ int   g_is64;                   // edge_index layout flag
__device__ int   g_deg[NNODES];
__device__ int   g_rowptr[NNODES + 1];
__device__ int   g_cursor[NNODES];
__device__ int   g_srcs[NEDGES];
__device__ int   g_eids[NEDGES];
__device__ float g_T[NNODES * 512];        // [A | S] per node
__device__ float g_z[NNODES * FOUT];       // inter-layer activations
__device__ float g_V[512 * 256];           // packed [Wd; Ws]
__device__ float g_We[FOUT * FEA];
__device__ float g_c1[FOUT];

// Fetch edge endpoint robustly: int32 layout (default) or int64 (stride 2).
__device__ __forceinline__ int edge_val(const int* ei, int E, int which, int e) {
    // which: 0 = src row, 1 = dst row
    if (g_is64) return ei[2 * (which * E + e)];     // little-endian low word
    return ei[which * E + e];
}

// ---------------- dtype detect + init ---------------------------------------
__global__ void detect_zero_kernel(const int* __restrict__ ei) {
    int i = blockIdx.x * blockDim.x + threadIdx.x;
    if (i < NNODES) g_deg[i] = 0;
    if (blockIdx.x == 0 && threadIdx.x == 0) {
        int all0 = 1;
        for (int k = 1; k < 128; k += 2)
            if (ei[k] != 0) { all0 = 0; break; }
        g_is64 = all0;
    }
}

__global__ void hist_kernel(const int* __restrict__ ei, int E) {
    int e = blockIdx.x * blockDim.x + threadIdx.x;
    if (e < E) {
        int d = edge_val(ei, E, 1, e);
        atomicAdd(&g_deg[d], 1);
    }
}

__global__ void scan_kernel(int n) {
    __shared__ int sh[1024];
    __shared__ int carry;
    int tid = threadIdx.x;
    if (tid == 0) { carry = 0; g_rowptr[0] = 0; }
    __syncthreads();
    for (int base = 0; base < n; base += 1024) {
        int i = base + tid;
        int val = (i < n) ? g_deg[i] : 0;
        sh[tid] = val;
        __syncthreads();
        for (int off = 1; off < 1024; off <<= 1) {
            int t = (tid >= off) ? sh[tid - off] : 0;
            __syncthreads();
            sh[tid] += t;
            __syncthreads();
        }
        if (i < n) {
            int incl = carry + sh[tid];
            g_rowptr[i + 1] = incl;
            g_cursor[i] = incl - val;
        }
        __syncthreads();
        if (tid == 1023) carry += sh[1023];
        __syncthreads();
    }
}

__global__ void fill_kernel(const int* __restrict__ ei, int E) {
    int e = blockIdx.x * blockDim.x + threadIdx.x;
    if (e < E) {
        int s = edge_val(ei, E, 0, e);
        int d = edge_val(ei, E, 1, e);
        int pos = atomicAdd(&g_cursor[d], 1);
        g_srcs[pos] = s;
        g_eids[pos] = e;
    }
}

// ---------------- per-layer weight pack -------------------------------------
__global__ void pack_kernel(const float* __restrict__ W, int K) {
    int ldw = 2 * K + FEA;
    int total = 512 * K + FOUT * FEA;
    for (int idx = blockIdx.x * blockDim.x + threadIdx.x; idx < total;
         idx += gridDim.x * blockDim.x) {
        if (idx < 512 * K) {
            int j = idx / K, k = idx - j * K;
            int row = j & 255;
            int off = (j >= 256) ? K : 0;
            g_V[idx] = W[row * ldw + off + k];
        } else {
            int i2 = idx - 512 * K;
            int c = i2 >> 4, k = i2 & 15;
            g_We[i2] = W[c * ldw + 2 * K + k];
        }
    }
}

__global__ void c1_kernel() {
    int c = threadIdx.x;
    float s = 0.f;
#pragma unroll
    for (int k = 0; k < FEA; k++) s += g_We[c * FEA + k];
    g_c1[c] = s;
}

// ---------------- GEMM: T[M x 512] = X[M x K] * g_V^T -----------------------
__global__ void sgemm512(const float* __restrict__ Xin, int M, int K) {
    const float* X = Xin ? Xin : g_z;
    const int BM = 128, BN = 64, BK = 16, TM = 8, TN = 4;
    __shared__ float As[BK][BM + 4];
    __shared__ float Bs[BK][BN];
    int tx = threadIdx.x & 15;
    int ty = threadIdx.x >> 4;
    int m0 = blockIdx.x * BM;
    int n0 = blockIdx.y * BN;
    float acc[TM][TN];
#pragma unroll
    for (int i = 0; i < TM; i++)
#pragma unroll
        for (int j = 0; j < TN; j++) acc[i][j] = 0.f;

    for (int k0 = 0; k0 < K; k0 += BK) {
        for (int i = threadIdx.x; i < BM * BK; i += 256) {
            int r = i >> 4, cc = i & 15;
            int gr = m0 + r;
            As[cc][r] = (gr < M) ? X[gr * K + k0 + cc] : 0.f;
        }
        for (int i = threadIdx.x; i < BN * BK; i += 256) {
            int r = i >> 4, cc = i & 15;
            Bs[cc][r] = g_V[(n0 + r) * K + k0 + cc];
        }
        __syncthreads();
#pragma unroll
        for (int kk = 0; kk < BK; kk++) {
            float ra[TM], rb[TN];
#pragma unroll
            for (int i = 0; i < TM; i++) ra[i] = As[kk][ty * TM + i];
#pragma unroll
            for (int j = 0; j < TN; j++) rb[j] = Bs[kk][tx * TN + j];
#pragma unroll
            for (int i = 0; i < TM; i++)
#pragma unroll
                for (int j = 0; j < TN; j++) acc[i][j] = fmaf(ra[i], rb[j], acc[i][j]);
        }
        __syncthreads();
    }
#pragma unroll
    for (int i = 0; i < TM; i++) {
        int gr = m0 + ty * TM + i;
        if (gr < M) {
#pragma unroll
            for (int j = 0; j < TN; j++)
                g_T[gr * 512 + n0 + tx * TN + j] = acc[i][j];
        }
    }
}

// ---------------- aggregation + epilogue ------------------------------------
// acc = (deg+1)*(A[v]+b) + S[v] + c1 + sum_{e->v} (S[src_e] + ea[e]·We[c])
__global__ void agg_kernel(const float* __restrict__ ea,
                           const float* __restrict__ bias,
                           const float* __restrict__ gg,
                           const float* __restrict__ beta,
                           const float* __restrict__ rm,
                           const float* __restrict__ rv,
                           float* __restrict__ outp, int do_bn) {
    int v = blockIdx.x;
    int c = threadIdx.x;
    float we[FEA];
#pragma unroll
    for (int k = 0; k < FEA; k++) we[k] = g_We[c * FEA + k];

    int start = g_rowptr[v];
    int end   = g_rowptr[v + 1];
    float a = g_T[v * 512 + c];
    float s = g_T[v * 512 + 256 + c];
    float acc = (float)(end - start + 1) * (a + bias[c]) + s + g_c1[c];

    __shared__ float ea_sh[16][FEA];
    __shared__ int   src_sh[16];
    for (int base = start; base < end; base += 16) {
        int m = end - base;
        if (m > 16) m = 16;
        int li = threadIdx.x;
        if (li < m * FEA) {
            int eidx = li >> 4, k = li & 15;
            int e = g_eids[base + eidx];
            ea_sh[eidx][k] = ea[e * FEA + k];
        }
        if (li < m) src_sh[li] = g_srcs[base + li];
        __syncthreads();
        for (int j = 0; j < m; j++) {
            int u = src_sh[j];
            float d = 0.f;
#pragma unroll
            for (int k = 0; k < FEA; k++) d = fmaf(ea_sh[j][k], we[k], d);
            acc += d + g_T[u * 512 + 256 + c];
        }
        __syncthreads();
    }

    float r = fmaxf(acc, 0.f);
    if (do_bn) {
        r = (r - rm[c]) * rsqrtf(rv[c] + EPSV) * gg[c] + beta[c];
        r = fmaxf(r, 0.f);
    }
    float* o = outp ? outp : g_z;
    o[v * FOUT + c] = r;
}

// ---------------- launch -----------------------------------------------------
extern "C" void kernel_launch(void* const* d_in, const int* in_sizes, int n_in,
                              void* d_out, int out_size) {
    const float* x   = (const float*)d_in[0];
    const int*   ei  = (const int*)d_in[1];     // int32 (JAX x64 disabled); int64 auto-detected
    const float* ea  = (const float*)d_in[2];
    const float* W[3] = {(const float*)d_in[3], (const float*)d_in[5], (const float*)d_in[7]};
    const float* b[3] = {(const float*)d_in[4], (const float*)d_in[6], (const float*)d_in[8]};
    const float* g0 = (const float*)d_in[9];
    const float* be0 = (const float*)d_in[10];
    const float* rm0 = (const float*)d_in[11];
    const float* rv0 = (const float*)d_in[12];
    const float* g1 = (const float*)d_in[13];
    const float* be1 = (const float*)d_in[14];
    const float* rm1 = (const float*)d_in[15];
    const float* rv1 = (const float*)d_in[16];
    float* outp = (float*)d_out;

    const int E = in_sizes[1] / 2;   // 320000 either way (element count is dtype-relative)
    const int M = NNODES;

    detect_zero_kernel<<<(NNODES + 255) / 256, 256>>>(ei);
    hist_kernel<<<(E + 255) / 256, 256>>>(ei, E);
    scan_kernel<<<1, 1024>>>(M);
    fill_kernel<<<(E + 255) / 256, 256>>>(ei, E);

    dim3 gemm_block(256);
    for (int layer = 0; layer < 3; layer++) {
        int K = (layer == 0) ? 128 : 256;
        const float* Xp = (layer == 0) ? x : nullptr;
        int packTotal = 512 * K + FOUT * FEA;
        pack_kernel<<<(packTotal + 255) / 256, 256>>>(W[layer], K);
        c1_kernel<<<1, 256>>>();
        dim3 grid((M + 127) / 128, 512 / 64);
        sgemm512<<<grid, gemm_block>>>(Xp, M, K);
        if (layer == 0)
            agg_kernel<<<M, 256>>>(ea, b[0], g0, be0, rm0, rv0, nullptr, 1);
        else if (layer == 1)
            agg_kernel<<<M, 256>>>(ea, b[1], g1, be1, rm1, rv1, nullptr, 1);
        else
            agg_kernel<<<M, 256>>>(ea, b[2], nullptr, nullptr, nullptr, nullptr, outp, 0);
    }
}

// round 4
// speedup vs baseline: 1.0772x; 1.0772x over previous
#include <cuda_runtime.h>
#include <cuda_bf16.h>

#define NNODES 20000
#define NEDGES 320000
#define FEA    16
#define FOUT   256
#define EPSV   1e-5f

// ---------------- scratch (static __device__ — no allocation allowed) -------
__device__ int   g_is64;                   // edge_index layout flag
__device__ int   g_deg[NNODES];
__device__ int   g_rowptr[NNODES + 1];
__device__ int   g_cursor[NNODES];
__device__ int   g_srcs[NEDGES];
__device__ int   g_eids[NEDGES];
__device__ float g_T[NNODES * 512];        // [A | S] per node
__device__ float g_z[NNODES * FOUT];       // inter-layer activations
__device__ float g_V[512 * 256];           // packed [Wd; Ws]
__device__ float g_We[FOUT * FEA];
__device__ float g_c1[FOUT];

__device__ __forceinline__ int edge_val(const int* ei, int E, int which, int e) {
    if (g_is64) return ei[2 * (which * E + e)];
    return ei[which * E + e];
}

// ---------------- dtype detect + init ---------------------------------------
__global__ void detect_zero_kernel(const int* __restrict__ ei) {
    int i = blockIdx.x * blockDim.x + threadIdx.x;
    if (i < NNODES) g_deg[i] = 0;
    if (blockIdx.x == 0 && threadIdx.x == 0) {
        int all0 = 1;
        for (int k = 1; k < 128; k += 2)
            if (ei[k] != 0) { all0 = 0; break; }
        g_is64 = all0;
    }
}

__global__ void hist_kernel(const int* __restrict__ ei, int E) {
    int e = blockIdx.x * blockDim.x + threadIdx.x;
    if (e < E) {
        int d = edge_val(ei, E, 1, e);
        atomicAdd(&g_deg[d], 1);
    }
}

__global__ void scan_kernel(int n) {
    __shared__ int sh[1024];
    __shared__ int carry;
    int tid = threadIdx.x;
    if (tid == 0) { carry = 0; g_rowptr[0] = 0; }
    __syncthreads();
    for (int base = 0; base < n; base += 1024) {
        int i = base + tid;
        int val = (i < n) ? g_deg[i] : 0;
        sh[tid] = val;
        __syncthreads();
        for (int off = 1; off < 1024; off <<= 1) {
            int t = (tid >= off) ? sh[tid - off] : 0;
            __syncthreads();
            sh[tid] += t;
            __syncthreads();
        }
        if (i < n) {
            int incl = carry + sh[tid];
            g_rowptr[i + 1] = incl;
            g_cursor[i] = incl - val;
        }
        __syncthreads();
        if (tid == 1023) carry += sh[1023];
        __syncthreads();
    }
}

__global__ void fill_kernel(const int* __restrict__ ei, int E) {
    int e = blockIdx.x * blockDim.x + threadIdx.x;
    if (e < E) {
        int s = edge_val(ei, E, 0, e);
        int d = edge_val(ei, E, 1, e);
        int pos = atomicAdd(&g_cursor[d], 1);
        g_srcs[pos] = s;
        g_eids[pos] = e;
    }
}

// ---------------- per-layer weight pack -------------------------------------
__global__ void pack_kernel(const float* __restrict__ W, int K) {
    int ldw = 2 * K + FEA;
    int total = 512 * K + FOUT * FEA;
    for (int idx = blockIdx.x * blockDim.x + threadIdx.x; idx < total;
         idx += gridDim.x * blockDim.x) {
        if (idx < 512 * K) {
            int j = idx / K, k = idx - j * K;
            int row = j & 255;
            int off = (j >= 256) ? K : 0;
            g_V[idx] = W[row * ldw + off + k];
        } else {
            int i2 = idx - 512 * K;
            int c = i2 >> 4, k = i2 & 15;
            g_We[i2] = W[c * ldw + 2 * K + k];
        }
    }
}

__global__ void c1_kernel() {
    int c = threadIdx.x;
    float s = 0.f;
#pragma unroll
    for (int k = 0; k < FEA; k++) s += g_We[c * FEA + k];
    g_c1[c] = s;
}

// ---------------- GEMM: T[M x 512] = X[M x K] * g_V^T -----------------------
// 128x128x16 tile, 256 threads, 8x8 microtile, float4 everywhere.
__global__ __launch_bounds__(256, 2) void sgemm512(const float* __restrict__ Xin,
                                                   int M, int K) {
    const float* X = Xin ? Xin : g_z;
    constexpr int BM = 128, BN = 128, BK = 16, TM = 8, TN = 8;
    __shared__ float As[BK][BM];
    __shared__ float Bs[BK][BN];
    int tid = threadIdx.x;
    int tx = tid & 15;            // n direction (16 x 8 = 128)
    int ty = tid >> 4;            // m direction (16 x 8 = 128)
    int m0 = blockIdx.x * BM;
    int n0 = blockIdx.y * BN;

    // load mapping: 512 float4 per tile, 2 per thread
    int lrow = tid >> 2;          // 0..63
    int lc4  = (tid & 3) * 4;     // 0,4,8,12

    float acc[TM][TN];
#pragma unroll
    for (int i = 0; i < TM; i++)
#pragma unroll
        for (int j = 0; j < TN; j++) acc[i][j] = 0.f;

    for (int k0 = 0; k0 < K; k0 += BK) {
#pragma unroll
        for (int h = 0; h < 2; h++) {
            int r = lrow + h * 64;
            int gr = m0 + r;
            float4 v = (gr < M) ? *(const float4*)&X[(size_t)gr * K + k0 + lc4]
                                : make_float4(0.f, 0.f, 0.f, 0.f);
            As[lc4 + 0][r] = v.x;
            As[lc4 + 1][r] = v.y;
            As[lc4 + 2][r] = v.z;
            As[lc4 + 3][r] = v.w;
        }
#pragma unroll
        for (int h = 0; h < 2; h++) {
            int r = lrow + h * 64;
            float4 v = *(const float4*)&g_V[(size_t)(n0 + r) * K + k0 + lc4];
            Bs[lc4 + 0][r] = v.x;
            Bs[lc4 + 1][r] = v.y;
            Bs[lc4 + 2][r] = v.z;
            Bs[lc4 + 3][r] = v.w;
        }
        __syncthreads();
#pragma unroll
        for (int kk = 0; kk < BK; kk++) {
            float ra[TM], rb[TN];
            *(float4*)&ra[0] = *(const float4*)&As[kk][ty * TM];
            *(float4*)&ra[4] = *(const float4*)&As[kk][ty * TM + 4];
            *(float4*)&rb[0] = *(const float4*)&Bs[kk][tx * TN];
            *(float4*)&rb[4] = *(const float4*)&Bs[kk][tx * TN + 4];
#pragma unroll
            for (int i = 0; i < TM; i++)
#pragma unroll
                for (int j = 0; j < TN; j++)
                    acc[i][j] = fmaf(ra[i], rb[j], acc[i][j]);
        }
        __syncthreads();
    }

#pragma unroll
    for (int i = 0; i < TM; i++) {
        int gr = m0 + ty * TM + i;
        if (gr < M) {
            float* dst = &g_T[(size_t)gr * 512 + n0 + tx * TN];
            *(float4*)&dst[0] = *(float4*)&acc[i][0];
            *(float4*)&dst[4] = *(float4*)&acc[i][4];
        }
    }
}

// ---------------- aggregation + epilogue ------------------------------------
// acc = (deg+1)*(A[v]+b) + S[v] + c1 + sum_{e->v} (S[src_e] + ea[e]·We[c])
__global__ void agg_kernel(const float* __restrict__ ea,
                           const float* __restrict__ bias,
                           const float* __restrict__ gg,
                           const float* __restrict__ beta,
                           const float* __restrict__ rm,
                           const float* __restrict__ rv,
                           float* __restrict__ outp, int do_bn) {
    int v = blockIdx.x;
    int c = threadIdx.x;
    float we[FEA];
#pragma unroll
    for (int k = 0; k < FEA; k++) we[k] = g_We[c * FEA + k];

    int start = g_rowptr[v];
    int end   = g_rowptr[v + 1];
    float a = g_T[v * 512 + c];
    float s = g_T[v * 512 + 256 + c];
    float acc = (float)(end - start + 1) * (a + bias[c]) + s + g_c1[c];

    __shared__ float ea_sh[16][FEA];
    __shared__ int   src_sh[16];
    for (int base = start; base < end; base += 16) {
        int m = end - base;
        if (m > 16) m = 16;
        int li = threadIdx.x;
        if (li < m * FEA) {
            int eidx = li >> 4, k = li & 15;
            int e = g_eids[base + eidx];
            ea_sh[eidx][k] = ea[e * FEA + k];
        }
        if (li < m) src_sh[li] = g_srcs[base + li];
        __syncthreads();
        for (int j = 0; j < m; j++) {
            int u = src_sh[j];
            float d = 0.f;
#pragma unroll
            for (int k = 0; k < FEA; k++) d = fmaf(ea_sh[j][k], we[k], d);
            acc += d + g_T[u * 512 + 256 + c];
        }
        __syncthreads();
    }

    float r = fmaxf(acc, 0.f);
    if (do_bn) {
        r = (r - rm[c]) * rsqrtf(rv[c] + EPSV) * gg[c] + beta[c];
        r = fmaxf(r, 0.f);
    }
    float* o = outp ? outp : g_z;
    o[v * FOUT + c] = r;
}

// ---------------- launch -----------------------------------------------------
extern "C" void kernel_launch(void* const* d_in, const int* in_sizes, int n_in,
                              void* d_out, int out_size) {
    const float* x   = (const float*)d_in[0];
    const int*   ei  = (const int*)d_in[1];
    const float* ea  = (const float*)d_in[2];
    const float* W[3] = {(const float*)d_in[3], (const float*)d_in[5], (const float*)d_in[7]};
    const float* b[3] = {(const float*)d_in[4], (const float*)d_in[6], (const float*)d_in[8]};
    const float* g0 = (const float*)d_in[9];
    const float* be0 = (const float*)d_in[10];
    const float* rm0 = (const float*)d_in[11];
    const float* rv0 = (const float*)d_in[12];
    const float* g1 = (const float*)d_in[13];
    const float* be1 = (const float*)d_in[14];
    const float* rm1 = (const float*)d_in[15];
    const float* rv1 = (const float*)d_in[16];
    float* outp = (float*)d_out;

    const int E = in_sizes[1] / 2;
    const int M = NNODES;

    detect_zero_kernel<<<(NNODES + 255) / 256, 256>>>(ei);
    hist_kernel<<<(E + 255) / 256, 256>>>(ei, E);
    scan_kernel<<<1, 1024>>>(M);
    fill_kernel<<<(E + 255) / 256, 256>>>(ei, E);

    for (int layer = 0; layer < 3; layer++) {
        int K = (layer == 0) ? 128 : 256;
        const float* Xp = (layer == 0) ? x : nullptr;
        int packTotal = 512 * K + FOUT * FEA;
        pack_kernel<<<(packTotal + 255) / 256, 256>>>(W[layer], K);
        c1_kernel<<<1, 256>>>();
        dim3 grid((M + 127) / 128, 512 / 128);
        sgemm512<<<grid, 256>>>(Xp, M, K);
        if (layer == 0)
            agg_kernel<<<M, 256>>>(ea, b[0], g0, be0, rm0, rv0, nullptr, 1);
        else if (layer == 1)
            agg_kernel<<<M, 256>>>(ea, b[1], g1, be1, rm1, rv1, nullptr, 1);
        else
            agg_kernel<<<M, 256>>>(ea, b[2], nullptr, nullptr, nullptr, nullptr, outp, 0);
    }
}

// round 7
// speedup vs baseline: 1.3112x; 1.2172x over previous
#include <cuda_runtime.h>
#include <cuda_bf16.h>

#define NNODES 20000
#define NEDGES 320000
#define FEA    16
#define FOUT   256
#define EPSV   1e-5f

// ---------------- scratch (static __device__ — no allocation allowed) -------
__device__ int   g_is64;
__device__ int   g_deg[NNODES];
__device__ int   g_rowptr[NNODES + 1];
__device__ int   g_cursor[NNODES];
__device__ int   g_srcs[NEDGES];
__device__ int   g_eids[NEDGES];
__device__ float g_EA[NNODES * FEA];       // per-node summed edge_attr (layer-invariant)
__device__ float g_T[NNODES * 512];        // [A | S] per node
__device__ float g_z[NNODES * FOUT];       // inter-layer activations
__device__ float g_V[512 * 256];           // packed [Wd; Ws]
__device__ float g_We[FOUT * FEA];
__device__ float g_c1[FOUT];

__device__ __forceinline__ int edge_val(const int* ei, int E, int which, int e) {
    if (g_is64) return ei[2 * (which * E + e)];
    return ei[which * E + e];
}

// ---------------- dtype detect + init ---------------------------------------
__global__ void detect_zero_kernel(const int* __restrict__ ei) {
    int i = blockIdx.x * blockDim.x + threadIdx.x;
    if (i < NNODES) g_deg[i] = 0;
    if (blockIdx.x == 0 && threadIdx.x == 0) {
        int all0 = 1;
        for (int k = 1; k < 128; k += 2)
            if (ei[k] != 0) { all0 = 0; break; }
        g_is64 = all0;
    }
}

__global__ void hist_kernel(const int* __restrict__ ei, int E) {
    int e = blockIdx.x * blockDim.x + threadIdx.x;
    if (e < E) {
        int d = edge_val(ei, E, 1, e);
        atomicAdd(&g_deg[d], 1);
    }
}

__global__ void scan_kernel(int n) {
    __shared__ int sh[1024];
    __shared__ int carry;
    int tid = threadIdx.x;
    if (tid == 0) { carry = 0; g_rowptr[0] = 0; }
    __syncthreads();
    for (int base = 0; base < n; base += 1024) {
        int i = base + tid;
        int val = (i < n) ? g_deg[i] : 0;
        sh[tid] = val;
        __syncthreads();
        for (int off = 1; off < 1024; off <<= 1) {
            int t = (tid >= off) ? sh[tid - off] : 0;
            __syncthreads();
            sh[tid] += t;
            __syncthreads();
        }
        if (i < n) {
            int incl = carry + sh[tid];
            g_rowptr[i + 1] = incl;
            g_cursor[i] = incl - val;
        }
        __syncthreads();
        if (tid == 1023) carry += sh[1023];
        __syncthreads();
    }
}

__global__ void fill_kernel(const int* __restrict__ ei, int E) {
    int e = blockIdx.x * blockDim.x + threadIdx.x;
    if (e < E) {
        int s = edge_val(ei, E, 0, e);
        int d = edge_val(ei, E, 1, e);
        int pos = atomicAdd(&g_cursor[d], 1);
        g_srcs[pos] = s;
        g_eids[pos] = e;
    }
}

// EA[v][k] = sum over incoming edges of ea[e][k]. One warp per node.
__global__ void ea_kernel(const float* __restrict__ ea) {
    int warp = (blockIdx.x * blockDim.x + threadIdx.x) >> 5;
    if (warp >= NNODES) return;
    int lane = threadIdx.x & 31;
    int j = lane >> 4, k = lane & 15;
    int start = g_rowptr[warp];
    int end   = g_rowptr[warp + 1];
    float acc = 0.f;
    for (int b = start + j; b < end; b += 2) {
        int e = g_eids[b];
        acc += ea[e * FEA + k];
    }
    acc += __shfl_down_sync(0xffffffffu, acc, 16);
    if (lane < 16) g_EA[warp * FEA + k] = acc;
}

// ---------------- per-layer weight pack -------------------------------------
__global__ void pack_kernel(const float* __restrict__ W, int K) {
    int ldw = 2 * K + FEA;
    int total = 512 * K + FOUT * FEA;
    for (int idx = blockIdx.x * blockDim.x + threadIdx.x; idx < total;
         idx += gridDim.x * blockDim.x) {
        if (idx < 512 * K) {
            int j = idx / K, k = idx - j * K;
            int row = j & 255;
            int off = (j >= 256) ? K : 0;
            g_V[idx] = W[row * ldw + off + k];
        } else {
            int i2 = idx - 512 * K;
            int c = i2 >> 4, k = i2 & 15;
            g_We[i2] = W[c * ldw + 2 * K + k];
        }
    }
}

__global__ void c1_kernel() {
    int c = threadIdx.x;
    float s = 0.f;
#pragma unroll
    for (int k = 0; k < FEA; k++) s += g_We[c * FEA + k];
    g_c1[c] = s;
}

// ---------------- GEMM: T[M x 512] = X[M x K] * g_V^T -----------------------
__global__ __launch_bounds__(256, 2) void sgemm512(const float* __restrict__ Xin,
                                                   int M, int K) {
    const float* X = Xin ? Xin : g_z;
    constexpr int BM = 128, BN = 128, BK = 16, TM = 8, TN = 8;
    __shared__ float As[BK][BM];
    __shared__ float Bs[BK][BN];
    int tid = threadIdx.x;
    int tx = tid & 15;
    int ty = tid >> 4;
    int m0 = blockIdx.x * BM;
    int n0 = blockIdx.y * BN;

    int lrow = tid >> 2;
    int lc4  = (tid & 3) * 4;

    float acc[TM][TN];
#pragma unroll
    for (int i = 0; i < TM; i++)
#pragma unroll
        for (int j = 0; j < TN; j++) acc[i][j] = 0.f;

    for (int k0 = 0; k0 < K; k0 += BK) {
#pragma unroll
        for (int h = 0; h < 2; h++) {
            int r = lrow + h * 64;
            int gr = m0 + r;
            float4 v = (gr < M) ? *(const float4*)&X[(size_t)gr * K + k0 + lc4]
                                : make_float4(0.f, 0.f, 0.f, 0.f);
            As[lc4 + 0][r] = v.x;
            As[lc4 + 1][r] = v.y;
            As[lc4 + 2][r] = v.z;
            As[lc4 + 3][r] = v.w;
        }
#pragma unroll
        for (int h = 0; h < 2; h++) {
            int r = lrow + h * 64;
            float4 v = *(const float4*)&g_V[(size_t)(n0 + r) * K + k0 + lc4];
            Bs[lc4 + 0][r] = v.x;
            Bs[lc4 + 1][r] = v.y;
            Bs[lc4 + 2][r] = v.z;
            Bs[lc4 + 3][r] = v.w;
        }
        __syncthreads();
#pragma unroll
        for (int kk = 0; kk < BK; kk++) {
            float ra[TM], rb[TN];
            *(float4*)&ra[0] = *(const float4*)&As[kk][ty * TM];
            *(float4*)&ra[4] = *(const float4*)&As[kk][ty * TM + 4];
            *(float4*)&rb[0] = *(const float4*)&Bs[kk][tx * TN];
            *(float4*)&rb[4] = *(const float4*)&Bs[kk][tx * TN + 4];
#pragma unroll
            for (int i = 0; i < TM; i++)
#pragma unroll
                for (int j = 0; j < TN; j++)
                    acc[i][j] = fmaf(ra[i], rb[j], acc[i][j]);
        }
        __syncthreads();
    }

#pragma unroll
    for (int i = 0; i < TM; i++) {
        int gr = m0 + ty * TM + i;
        if (gr < M) {
            float* dst = &g_T[(size_t)gr * 512 + n0 + tx * TN];
            *(float4*)&dst[0] = *(float4*)&acc[i][0];
            *(float4*)&dst[4] = *(float4*)&acc[i][4];
        }
    }
}

// ---------------- aggregation + epilogue ------------------------------------
// acc = (deg+1)*(A[v]+b) + S[v] + c1 + We[c]·EA[v] + sum_{e->v} S[src_e]
__global__ __launch_bounds__(256) void agg_kernel(const float* __restrict__ bias,
                           const float* __restrict__ gg,
                           const float* __restrict__ beta,
                           const float* __restrict__ rm,
                           const float* __restrict__ rv,
                           float* __restrict__ outp, int do_bn) {
    int v = blockIdx.x;
    int c = threadIdx.x;
    int lane = c & 31;

    __shared__ float ea_sh[FEA];
    if (c < FEA) ea_sh[c] = g_EA[v * FEA + c];
    __syncthreads();

    float dot = 0.f;
#pragma unroll
    for (int k = 0; k < FEA; k++) dot = fmaf(g_We[c * FEA + k], ea_sh[k], dot);

    int start = g_rowptr[v];
    int end   = g_rowptr[v + 1];
    float a = g_T[(size_t)v * 512 + c];
    float s = g_T[(size_t)v * 512 + 256 + c];
    float acc0 = (float)(end - start + 1) * (a + bias[c]) + s + g_c1[c] + dot;
    float acc1 = 0.f, acc2 = 0.f, acc3 = 0.f;

    const float* Sbase = &g_T[256];
    for (int base = start; base < end; base += 32) {
        int m = end - base;
        if (m > 32) m = 32;
        int src = (lane < m) ? g_srcs[base + lane] : 0;
        int j = 0;
        for (; j + 4 <= m; j += 4) {
            int u0 = __shfl_sync(0xffffffffu, src, j + 0);
            int u1 = __shfl_sync(0xffffffffu, src, j + 1);
            int u2 = __shfl_sync(0xffffffffu, src, j + 2);
            int u3 = __shfl_sync(0xffffffffu, src, j + 3);
            float v0 = Sbase[(size_t)u0 * 512 + c];
            float v1 = Sbase[(size_t)u1 * 512 + c];
            float v2 = Sbase[(size_t)u2 * 512 + c];
            float v3 = Sbase[(size_t)u3 * 512 + c];
            acc0 += v0; acc1 += v1; acc2 += v2; acc3 += v3;
        }
        for (; j < m; j++) {
            int u = __shfl_sync(0xffffffffu, src, j);
            acc0 += Sbase[(size_t)u * 512 + c];
        }
    }
    float acc = (acc0 + acc1) + (acc2 + acc3);

    float r = fmaxf(acc, 0.f);
    if (do_bn) {
        r = (r - rm[c]) * rsqrtf(rv[c] + EPSV) * gg[c] + beta[c];
        r = fmaxf(r, 0.f);
    }
    float* o = outp ? outp : g_z;
    o[(size_t)v * FOUT + c] = r;
}

// ---------------- launch -----------------------------------------------------
extern "C" void kernel_launch(void* const* d_in, const int* in_sizes, int n_in,
                              void* d_out, int out_size) {
    const float* x   = (const float*)d_in[0];
    const int*   ei  = (const int*)d_in[1];
    const float* ea  = (const float*)d_in[2];
    const float* W[3] = {(const float*)d_in[3], (const float*)d_in[5], (const float*)d_in[7]};
    const float* b[3] = {(const float*)d_in[4], (const float*)d_in[6], (const float*)d_in[8]};
    const float* g0 = (const float*)d_in[9];
    const float* be0 = (const float*)d_in[10];
    const float* rm0 = (const float*)d_in[11];
    const float* rv0 = (const float*)d_in[12];
    const float* g1 = (const float*)d_in[13];
    const float* be1 = (const float*)d_in[14];
    const float* rm1 = (const float*)d_in[15];
    const float* rv1 = (const float*)d_in[16];
    float* outp = (float*)d_out;

    const int E = in_sizes[1] / 2;
    const int M = NNODES;

    detect_zero_kernel<<<(NNODES + 255) / 256, 256>>>(ei);
    hist_kernel<<<(E + 255) / 256, 256>>>(ei, E);
    scan_kernel<<<1, 1024>>>(M);
    fill_kernel<<<(E + 255) / 256, 256>>>(ei, E);
    ea_kernel<<<(NNODES * 32 + 255) / 256, 256>>>(ea);

    for (int layer = 0; layer < 3; layer++) {
        int K = (layer == 0) ? 128 : 256;
        const float* Xp = (layer == 0) ? x : nullptr;
        int packTotal = 512 * K + FOUT * FEA;
        pack_kernel<<<(packTotal + 255) / 256, 256>>>(W[layer], K);
        c1_kernel<<<1, 256>>>();
        dim3 grid((M + 127) / 128, 512 / 128);
        sgemm512<<<grid, 256>>>(Xp, M, K);
        if (layer == 0)
            agg_kernel<<<M, 256>>>(b[0], g0, be0, rm0, rv0, nullptr, 1);
        else if (layer == 1)
            agg_kernel<<<M, 256>>>(b[1], g1, be1, rm1, rv1, nullptr, 1);
        else
            agg_kernel<<<M, 256>>>(b[2], nullptr, nullptr, nullptr, nullptr, outp, 0);
    }
}

// round 8
// speedup vs baseline: 1.6488x; 1.2575x over previous
#include <cuda_runtime.h>
#include <cuda_bf16.h>
#include <cstdint>

#define NNODES 20000
#define NEDGES 320000
#define FEA    16
#define FOUT   256
#define EPSV   1e-5f

// ---------------- scratch (static __device__ — no allocation allowed) -------
__device__ int   g_is64;
__device__ int   g_deg[NNODES];
__device__ int   g_rowptr[NNODES + 1];
__device__ int   g_cursor[NNODES];
__device__ int   g_srcs[NEDGES];
__device__ int   g_eids[NEDGES];
__device__ float g_EA[NNODES * FEA];       // per-node summed edge_attr (layer-invariant)
__device__ float g_T[NNODES * 512];        // [A | S] per node
__device__ float g_z[NNODES * FOUT];       // inter-layer activations
__device__ float g_V[512 * 256];           // packed [Wd; Ws]
__device__ float g_We[FOUT * FEA];
__device__ float g_c1[FOUT];

__device__ __forceinline__ int edge_val(const int* ei, int E, int which, int e) {
    if (g_is64) return ei[2 * (which * E + e)];
    return ei[which * E + e];
}

__device__ __forceinline__ uint32_t f2tf32(float v) {
    uint32_t t;
    asm("cvt.rna.tf32.f32 %0, %1;" : "=r"(t) : "f"(v));
    return t;
}

// ---------------- dtype detect + init ---------------------------------------
__global__ void detect_zero_kernel(const int* __restrict__ ei) {
    int i = blockIdx.x * blockDim.x + threadIdx.x;
    if (i < NNODES) g_deg[i] = 0;
    if (blockIdx.x == 0 && threadIdx.x == 0) {
        int all0 = 1;
        for (int k = 1; k < 128; k += 2)
            if (ei[k] != 0) { all0 = 0; break; }
        g_is64 = all0;
    }
}

__global__ void hist_kernel(const int* __restrict__ ei, int E) {
    int e = blockIdx.x * blockDim.x + threadIdx.x;
    if (e < E) {
        int d = edge_val(ei, E, 1, e);
        atomicAdd(&g_deg[d], 1);
    }
}

__global__ void scan_kernel(int n) {
    __shared__ int sh[1024];
    __shared__ int carry;
    int tid = threadIdx.x;
    if (tid == 0) { carry = 0; g_rowptr[0] = 0; }
    __syncthreads();
    for (int base = 0; base < n; base += 1024) {
        int i = base + tid;
        int val = (i < n) ? g_deg[i] : 0;
        sh[tid] = val;
        __syncthreads();
        for (int off = 1; off < 1024; off <<= 1) {
            int t = (tid >= off) ? sh[tid - off] : 0;
            __syncthreads();
            sh[tid] += t;
            __syncthreads();
        }
        if (i < n) {
            int incl = carry + sh[tid];
            g_rowptr[i + 1] = incl;
            g_cursor[i] = incl - val;
        }
        __syncthreads();
        if (tid == 1023) carry += sh[1023];
        __syncthreads();
    }
}

__global__ void fill_kernel(const int* __restrict__ ei, int E) {
    int e = blockIdx.x * blockDim.x + threadIdx.x;
    if (e < E) {
        int s = edge_val(ei, E, 0, e);
        int d = edge_val(ei, E, 1, e);
        int pos = atomicAdd(&g_cursor[d], 1);
        g_srcs[pos] = s;
        g_eids[pos] = e;
    }
}

// EA[v][k] = sum over incoming edges of ea[e][k]. One warp per node.
__global__ void ea_kernel(const float* __restrict__ ea) {
    int warp = (blockIdx.x * blockDim.x + threadIdx.x) >> 5;
    if (warp >= NNODES) return;
    int lane = threadIdx.x & 31;
    int j = lane >> 4, k = lane & 15;
    int start = g_rowptr[warp];
    int end   = g_rowptr[warp + 1];
    float acc = 0.f;
    for (int b = start + j; b < end; b += 2) {
        int e = g_eids[b];
        acc += ea[e * FEA + k];
    }
    acc += __shfl_down_sync(0xffffffffu, acc, 16);
    if (lane < 16) g_EA[warp * FEA + k] = acc;
}

// ---------------- per-layer weight pack -------------------------------------
__global__ void pack_kernel(const float* __restrict__ W, int K) {
    int ldw = 2 * K + FEA;
    int total = 512 * K + FOUT * FEA;
    for (int idx = blockIdx.x * blockDim.x + threadIdx.x; idx < total;
         idx += gridDim.x * blockDim.x) {
        if (idx < 512 * K) {
            int j = idx / K, k = idx - j * K;
            int row = j & 255;
            int off = (j >= 256) ? K : 0;
            g_V[idx] = W[row * ldw + off + k];
        } else {
            int i2 = idx - 512 * K;
            int c = i2 >> 4, k = i2 & 15;
            g_We[i2] = W[c * ldw + 2 * K + k];
        }
    }
}

__global__ void c1_kernel() {
    int c = threadIdx.x;
    float s = 0.f;
#pragma unroll
    for (int k = 0; k < FEA; k++) s += g_We[c * FEA + k];
    g_c1[c] = s;
}

// ---------------- TF32 tensor-core GEMM: T[M x 512] = X[M x K] * g_V^T -------
// 128x128x32 block tile, 8 warps (2x4), warp tile 64x32, mma.m16n8k8.tf32.
#define SM_STRIDE 132
__global__ __launch_bounds__(256, 2) void tgemm512(const float* __restrict__ Xin,
                                                   int M, int K) {
    const float* X = Xin ? Xin : g_z;
    constexpr int BM = 128, BK = 32;
    __shared__ uint32_t As[BK][SM_STRIDE];   // As[k][m], tf32 bits
    __shared__ uint32_t Bs[BK][SM_STRIDE];   // Bs[k][n]
    int tid  = threadIdx.x;
    int lane = tid & 31;
    int warp = tid >> 5;
    int gid  = lane >> 2;     // 0..7
    int tig  = lane & 3;      // 0..3
    int warpM = warp >> 2;    // 0..1  (64 rows each)
    int warpN = warp & 3;     // 0..3  (32 cols each)
    int m0 = blockIdx.x * BM;
    int n0 = blockIdx.y * BM; // BN == BM == 128

    float acc[4][4][4];
#pragma unroll
    for (int mt = 0; mt < 4; mt++)
#pragma unroll
        for (int nt = 0; nt < 4; nt++)
#pragma unroll
            for (int f = 0; f < 4; f++) acc[mt][nt][f] = 0.f;

    for (int k0 = 0; k0 < K; k0 += BK) {
        // stage A: 128 rows x 32 cols, 1024 float4 over 256 threads
#pragma unroll
        for (int j = 0; j < 4; j++) {
            int idx = tid + j * 256;
            int r = idx >> 3;            // m row 0..127
            int c4 = (idx & 7) * 4;      // k col
            int gr = m0 + r;
            float4 v = (gr < M) ? *(const float4*)&X[(size_t)gr * K + k0 + c4]
                                : make_float4(0.f, 0.f, 0.f, 0.f);
            As[c4 + 0][r] = f2tf32(v.x);
            As[c4 + 1][r] = f2tf32(v.y);
            As[c4 + 2][r] = f2tf32(v.z);
            As[c4 + 3][r] = f2tf32(v.w);
        }
        // stage B: 128 n-rows (always valid; 512 total) x 32 cols
#pragma unroll
        for (int j = 0; j < 4; j++) {
            int idx = tid + j * 256;
            int r = idx >> 3;
            int c4 = (idx & 7) * 4;
            float4 v = *(const float4*)&g_V[(size_t)(n0 + r) * K + k0 + c4];
            Bs[c4 + 0][r] = f2tf32(v.x);
            Bs[c4 + 1][r] = f2tf32(v.y);
            Bs[c4 + 2][r] = f2tf32(v.z);
            Bs[c4 + 3][r] = f2tf32(v.w);
        }
        __syncthreads();

#pragma unroll
        for (int ks = 0; ks < BK; ks += 8) {
            uint32_t a[4][4];
#pragma unroll
            for (int mt = 0; mt < 4; mt++) {
                int m = warpM * 64 + mt * 16 + gid;
                a[mt][0] = As[ks + tig][m];
                a[mt][1] = As[ks + tig][m + 8];
                a[mt][2] = As[ks + tig + 4][m];
                a[mt][3] = As[ks + tig + 4][m + 8];
            }
            uint32_t b[4][2];
#pragma unroll
            for (int nt = 0; nt < 4; nt++) {
                int n = warpN * 32 + nt * 8 + gid;
                b[nt][0] = Bs[ks + tig][n];
                b[nt][1] = Bs[ks + tig + 4][n];
            }
#pragma unroll
            for (int mt = 0; mt < 4; mt++)
#pragma unroll
                for (int nt = 0; nt < 4; nt++) {
                    asm volatile(
                        "mma.sync.aligned.m16n8k8.row.col.f32.tf32.tf32.f32 "
                        "{%0,%1,%2,%3}, {%4,%5,%6,%7}, {%8,%9}, {%0,%1,%2,%3};"
                        : "+f"(acc[mt][nt][0]), "+f"(acc[mt][nt][1]),
                          "+f"(acc[mt][nt][2]), "+f"(acc[mt][nt][3])
                        : "r"(a[mt][0]), "r"(a[mt][1]), "r"(a[mt][2]), "r"(a[mt][3]),
                          "r"(b[nt][0]), "r"(b[nt][1]));
                }
        }
        __syncthreads();
    }

#pragma unroll
    for (int mt = 0; mt < 4; mt++) {
        int r0 = m0 + warpM * 64 + mt * 16 + gid;
        int r1 = r0 + 8;
#pragma unroll
        for (int nt = 0; nt < 4; nt++) {
            int col = n0 + warpN * 32 + nt * 8 + tig * 2;
            if (r0 < M)
                *(float2*)&g_T[(size_t)r0 * 512 + col] =
                    make_float2(acc[mt][nt][0], acc[mt][nt][1]);
            if (r1 < M)
                *(float2*)&g_T[(size_t)r1 * 512 + col] =
                    make_float2(acc[mt][nt][2], acc[mt][nt][3]);
        }
    }
}

// ---------------- aggregation + epilogue ------------------------------------
// acc = (deg+1)*(A[v]+b) + S[v] + c1 + We[c]·EA[v] + sum_{e->v} S[src_e]
__global__ __launch_bounds__(256) void agg_kernel(const float* __restrict__ bias,
                           const float* __restrict__ gg,
                           const float* __restrict__ beta,
                           const float* __restrict__ rm,
                           const float* __restrict__ rv,
                           float* __restrict__ outp, int do_bn) {
    int v = blockIdx.x;
    int c = threadIdx.x;
    int lane = c & 31;

    __shared__ float ea_sh[FEA];
    if (c < FEA) ea_sh[c] = g_EA[v * FEA + c];
    __syncthreads();

    float dot = 0.f;
#pragma unroll
    for (int k = 0; k < FEA; k++) dot = fmaf(g_We[c * FEA + k], ea_sh[k], dot);

    int start = g_rowptr[v];
    int end   = g_rowptr[v + 1];
    float a = g_T[(size_t)v * 512 + c];
    float s = g_T[(size_t)v * 512 + 256 + c];
    float acc0 = (float)(end - start + 1) * (a + bias[c]) + s + g_c1[c] + dot;
    float acc1 = 0.f, acc2 = 0.f, acc3 = 0.f;

    const float* Sbase = &g_T[256];
    for (int base = start; base < end; base += 32) {
        int m = end - base;
        if (m > 32) m = 32;
        int src = (lane < m) ? g_srcs[base + lane] : 0;
        int j = 0;
        for (; j + 4 <= m; j += 4) {
            int u0 = __shfl_sync(0xffffffffu, src, j + 0);
            int u1 = __shfl_sync(0xffffffffu, src, j + 1);
            int u2 = __shfl_sync(0xffffffffu, src, j + 2);
            int u3 = __shfl_sync(0xffffffffu, src, j + 3);
            float v0 = Sbase[(size_t)u0 * 512 + c];
            float v1 = Sbase[(size_t)u1 * 512 + c];
            float v2 = Sbase[(size_t)u2 * 512 + c];
            float v3 = Sbase[(size_t)u3 * 512 + c];
            acc0 += v0; acc1 += v1; acc2 += v2; acc3 += v3;
        }
        for (; j < m; j++) {
            int u = __shfl_sync(0xffffffffu, src, j);
            acc0 += Sbase[(size_t)u * 512 + c];
        }
    }
    float acc = (acc0 + acc1) + (acc2 + acc3);

    float r = fmaxf(acc, 0.f);
    if (do_bn) {
        r = (r - rm[c]) * rsqrtf(rv[c] + EPSV) * gg[c] + beta[c];
        r = fmaxf(r, 0.f);
    }
    float* o = outp ? outp : g_z;
    o[(size_t)v * FOUT + c] = r;
}

// ---------------- launch -----------------------------------------------------
extern "C" void kernel_launch(void* const* d_in, const int* in_sizes, int n_in,
                              void* d_out, int out_size) {
    const float* x   = (const float*)d_in[0];
    const int*   ei  = (const int*)d_in[1];
    const float* ea  = (const float*)d_in[2];
    const float* W[3] = {(const float*)d_in[3], (const float*)d_in[5], (const float*)d_in[7]};
    const float* b[3] = {(const float*)d_in[4], (const float*)d_in[6], (const float*)d_in[8]};
    const float* g0 = (const float*)d_in[9];
    const float* be0 = (const float*)d_in[10];
    const float* rm0 = (const float*)d_in[11];
    const float* rv0 = (const float*)d_in[12];
    const float* g1 = (const float*)d_in[13];
    const float* be1 = (const float*)d_in[14];
    const float* rm1 = (const float*)d_in[15];
    const float* rv1 = (const float*)d_in[16];
    float* outp = (float*)d_out;

    const int E = in_sizes[1] / 2;
    const int M = NNODES;

    detect_zero_kernel<<<(NNODES + 255) / 256, 256>>>(ei);
    hist_kernel<<<(E + 255) / 256, 256>>>(ei, E);
    scan_kernel<<<1, 1024>>>(M);
    fill_kernel<<<(E + 255) / 256, 256>>>(ei, E);
    ea_kernel<<<(NNODES * 32 + 255) / 256, 256>>>(ea);

    for (int layer = 0; layer < 3; layer++) {
        int K = (layer == 0) ? 128 : 256;
        const float* Xp = (layer == 0) ? x : nullptr;
        int packTotal = 512 * K + FOUT * FEA;
        pack_kernel<<<(packTotal + 255) / 256, 256>>>(W[layer], K);
        c1_kernel<<<1, 256>>>();
        dim3 grid((M + 127) / 128, 512 / 128);
        tgemm512<<<grid, 256>>>(Xp, M, K);
        if (layer == 0)
            agg_kernel<<<M, 256>>>(b[0], g0, be0, rm0, rv0, nullptr, 1);
        else if (layer == 1)
            agg_kernel<<<M, 256>>>(b[1], g1, be1, rm1, rv1, nullptr, 1);
        else
            agg_kernel<<<M, 256>>>(b[2], nullptr, nullptr, nullptr, nullptr, outp, 0);
    }
}

// round 9
// speedup vs baseline: 2.9246x; 1.7737x over previous
#include <cuda_runtime.h>
#include <cuda_bf16.h>
#include <cstdint>

#define NNODES 20000
#define NEDGES 320000
#define FEA    16
#define FOUT   256
#define EPSV   1e-5f

// ---------------- scratch (static __device__ — no allocation allowed) -------
__device__ int   g_is64;
__device__ int   g_deg[NNODES];
__device__ int   g_rowptr[NNODES + 1];
__device__ int   g_cursor[NNODES];
__device__ int   g_srcs[NEDGES];
__device__ int   g_eids[NEDGES];
__device__ float g_EA[NNODES * FEA];       // per-node summed edge_attr (layer-invariant)
__device__ float g_WEA[NNODES * FOUT];     // per-layer We @ EA[v]
__device__ float g_T[NNODES * 512];        // [A | S] per node
__device__ float g_z[NNODES * FOUT];       // inter-layer activations
__device__ float g_V[512 * 256];           // packed [Wd; Ws]
__device__ float g_We[FOUT * FEA];         // [c][k]
__device__ float g_WeT[FEA * FOUT];        // [k][c]  (coalesced per-channel reads)
__device__ float g_c1[FOUT];

__device__ __forceinline__ int edge_val(const int* ei, int E, int which, int e) {
    if (g_is64) return ei[2 * (which * E + e)];
    return ei[which * E + e];
}

__device__ __forceinline__ uint32_t f2tf32(float v) {
    uint32_t t;
    asm("cvt.rna.tf32.f32 %0, %1;" : "=r"(t) : "f"(v));
    return t;
}

// ---------------- dtype detect + init ---------------------------------------
__global__ void detect_zero_kernel(const int* __restrict__ ei) {
    int i = blockIdx.x * blockDim.x + threadIdx.x;
    if (i < NNODES) g_deg[i] = 0;
    if (blockIdx.x == 0 && threadIdx.x == 0) {
        int all0 = 1;
        for (int k = 1; k < 128; k += 2)
            if (ei[k] != 0) { all0 = 0; break; }
        g_is64 = all0;
    }
}

__global__ void hist_kernel(const int* __restrict__ ei, int E) {
    int e = blockIdx.x * blockDim.x + threadIdx.x;
    if (e < E) {
        int d = edge_val(ei, E, 1, e);
        atomicAdd(&g_deg[d], 1);
    }
}

__global__ void scan_kernel(int n) {
    __shared__ int sh[1024];
    __shared__ int carry;
    int tid = threadIdx.x;
    if (tid == 0) { carry = 0; g_rowptr[0] = 0; }
    __syncthreads();
    for (int base = 0; base < n; base += 1024) {
        int i = base + tid;
        int val = (i < n) ? g_deg[i] : 0;
        sh[tid] = val;
        __syncthreads();
        for (int off = 1; off < 1024; off <<= 1) {
            int t = (tid >= off) ? sh[tid - off] : 0;
            __syncthreads();
            sh[tid] += t;
            __syncthreads();
        }
        if (i < n) {
            int incl = carry + sh[tid];
            g_rowptr[i + 1] = incl;
            g_cursor[i] = incl - val;
        }
        __syncthreads();
        if (tid == 1023) carry += sh[1023];
        __syncthreads();
    }
}

__global__ void fill_kernel(const int* __restrict__ ei, int E) {
    int e = blockIdx.x * blockDim.x + threadIdx.x;
    if (e < E) {
        int s = edge_val(ei, E, 0, e);
        int d = edge_val(ei, E, 1, e);
        int pos = atomicAdd(&g_cursor[d], 1);
        g_srcs[pos] = s;
        g_eids[pos] = e;
    }
}

// EA[v][k] = sum over incoming edges of ea[e][k]. One warp per node.
__global__ void ea_kernel(const float* __restrict__ ea) {
    int warp = (blockIdx.x * blockDim.x + threadIdx.x) >> 5;
    if (warp >= NNODES) return;
    int lane = threadIdx.x & 31;
    int j = lane >> 4, k = lane & 15;
    int start = g_rowptr[warp];
    int end   = g_rowptr[warp + 1];
    float acc = 0.f;
    for (int b = start + j; b < end; b += 2) {
        int e = g_eids[b];
        acc += ea[e * FEA + k];
    }
    acc += __shfl_down_sync(0xffffffffu, acc, 16);
    if (lane < 16) g_EA[warp * FEA + k] = acc;
}

// ---------------- per-layer weight pack -------------------------------------
__global__ void pack_kernel(const float* __restrict__ W, int K) {
    int ldw = 2 * K + FEA;
    int total = 512 * K + FOUT * FEA;
    for (int idx = blockIdx.x * blockDim.x + threadIdx.x; idx < total;
         idx += gridDim.x * blockDim.x) {
        if (idx < 512 * K) {
            int j = idx / K, k = idx - j * K;
            int row = j & 255;
            int off = (j >= 256) ? K : 0;
            g_V[idx] = W[row * ldw + off + k];
        } else {
            int i2 = idx - 512 * K;
            int c = i2 >> 4, k = i2 & 15;
            float w = W[c * ldw + 2 * K + k];
            g_We[i2] = w;
            g_WeT[k * FOUT + c] = w;
        }
    }
}

__global__ void c1_kernel() {
    int c = threadIdx.x;
    float s = 0.f;
#pragma unroll
    for (int k = 0; k < FEA; k++) s += g_We[c * FEA + k];
    g_c1[c] = s;
}

// WEA[v][c] = dot(We[c], EA[v]). 8 nodes per block, fully coalesced.
__global__ __launch_bounds__(256) void wea_kernel() {
    __shared__ float sEA[8][FEA + 1];
    int tid = threadIdx.x;
    int v0 = blockIdx.x * 8;
    if (tid < 8 * FEA) sEA[tid >> 4][tid & 15] = g_EA[v0 * FEA + tid];
    __syncthreads();
    float wec[FEA];
#pragma unroll
    for (int k = 0; k < FEA; k++) wec[k] = g_WeT[k * FOUT + tid];
#pragma unroll
    for (int j = 0; j < 8; j++) {
        float d = 0.f;
#pragma unroll
        for (int k = 0; k < FEA; k++) d = fmaf(wec[k], sEA[j][k], d);
        g_WEA[(size_t)(v0 + j) * FOUT + tid] = d;
    }
}

// ---------------- TF32 tensor-core GEMM: T[M x 512] = X[M x K] * g_V^T -------
#define SM_STRIDE 132
__global__ __launch_bounds__(256, 2) void tgemm512(const float* __restrict__ Xin,
                                                   int M, int K) {
    const float* X = Xin ? Xin : g_z;
    constexpr int BM = 128, BK = 32;
    __shared__ uint32_t As[BK][SM_STRIDE];
    __shared__ uint32_t Bs[BK][SM_STRIDE];
    int tid  = threadIdx.x;
    int lane = tid & 31;
    int warp = tid >> 5;
    int gid  = lane >> 2;
    int tig  = lane & 3;
    int warpM = warp >> 2;
    int warpN = warp & 3;
    int m0 = blockIdx.x * BM;
    int n0 = blockIdx.y * BM;

    float acc[4][4][4];
#pragma unroll
    for (int mt = 0; mt < 4; mt++)
#pragma unroll
        for (int nt = 0; nt < 4; nt++)
#pragma unroll
            for (int f = 0; f < 4; f++) acc[mt][nt][f] = 0.f;

    for (int k0 = 0; k0 < K; k0 += BK) {
#pragma unroll
        for (int j = 0; j < 4; j++) {
            int idx = tid + j * 256;
            int r = idx >> 3;
            int c4 = (idx & 7) * 4;
            int gr = m0 + r;
            float4 v = (gr < M) ? *(const float4*)&X[(size_t)gr * K + k0 + c4]
                                : make_float4(0.f, 0.f, 0.f, 0.f);
            As[c4 + 0][r] = f2tf32(v.x);
            As[c4 + 1][r] = f2tf32(v.y);
            As[c4 + 2][r] = f2tf32(v.z);
            As[c4 + 3][r] = f2tf32(v.w);
        }
#pragma unroll
        for (int j = 0; j < 4; j++) {
            int idx = tid + j * 256;
            int r = idx >> 3;
            int c4 = (idx & 7) * 4;
            float4 v = *(const float4*)&g_V[(size_t)(n0 + r) * K + k0 + c4];
            Bs[c4 + 0][r] = f2tf32(v.x);
            Bs[c4 + 1][r] = f2tf32(v.y);
            Bs[c4 + 2][r] = f2tf32(v.z);
            Bs[c4 + 3][r] = f2tf32(v.w);
        }
        __syncthreads();

#pragma unroll
        for (int ks = 0; ks < BK; ks += 8) {
            uint32_t a[4][4];
#pragma unroll
            for (int mt = 0; mt < 4; mt++) {
                int m = warpM * 64 + mt * 16 + gid;
                a[mt][0] = As[ks + tig][m];
                a[mt][1] = As[ks + tig][m + 8];
                a[mt][2] = As[ks + tig + 4][m];
                a[mt][3] = As[ks + tig + 4][m + 8];
            }
            uint32_t b[4][2];
#pragma unroll
            for (int nt = 0; nt < 4; nt++) {
                int n = warpN * 32 + nt * 8 + gid;
                b[nt][0] = Bs[ks + tig][n];
                b[nt][1] = Bs[ks + tig + 4][n];
            }
#pragma unroll
            for (int mt = 0; mt < 4; mt++)
#pragma unroll
                for (int nt = 0; nt < 4; nt++) {
                    asm volatile(
                        "mma.sync.aligned.m16n8k8.row.col.f32.tf32.tf32.f32 "
                        "{%0,%1,%2,%3}, {%4,%5,%6,%7}, {%8,%9}, {%0,%1,%2,%3};"
                        : "+f"(acc[mt][nt][0]), "+f"(acc[mt][nt][1]),
                          "+f"(acc[mt][nt][2]), "+f"(acc[mt][nt][3])
                        : "r"(a[mt][0]), "r"(a[mt][1]), "r"(a[mt][2]), "r"(a[mt][3]),
                          "r"(b[nt][0]), "r"(b[nt][1]));
                }
        }
        __syncthreads();
    }

#pragma unroll
    for (int mt = 0; mt < 4; mt++) {
        int r0 = m0 + warpM * 64 + mt * 16 + gid;
        int r1 = r0 + 8;
#pragma unroll
        for (int nt = 0; nt < 4; nt++) {
            int col = n0 + warpN * 32 + nt * 8 + tig * 2;
            if (r0 < M)
                *(float2*)&g_T[(size_t)r0 * 512 + col] =
                    make_float2(acc[mt][nt][0], acc[mt][nt][1]);
            if (r1 < M)
                *(float2*)&g_T[(size_t)r1 * 512 + col] =
                    make_float2(acc[mt][nt][2], acc[mt][nt][3]);
        }
    }
}

// ---------------- aggregation + epilogue ------------------------------------
// acc = (deg+1)*(A[v]+b) + S[v] + c1 + WEA[v][c] + sum_{e->v} S[src_e]
__global__ __launch_bounds__(256) void agg_kernel(const float* __restrict__ bias,
                           const float* __restrict__ gg,
                           const float* __restrict__ beta,
                           const float* __restrict__ rm,
                           const float* __restrict__ rv,
                           float* __restrict__ outp, int do_bn) {
    int v = blockIdx.x;
    int c = threadIdx.x;
    int lane = c & 31;

    int start = g_rowptr[v];
    int end   = g_rowptr[v + 1];
    float a = g_T[(size_t)v * 512 + c];
    float s = g_T[(size_t)v * 512 + 256 + c];
    float dot = g_WEA[(size_t)v * FOUT + c];
    float acc0 = (float)(end - start + 1) * (a + bias[c]) + s + g_c1[c] + dot;
    float acc1 = 0.f, acc2 = 0.f, acc3 = 0.f;

    const float* Sbase = &g_T[256];
    for (int base = start; base < end; base += 32) {
        int m = end - base;
        if (m > 32) m = 32;
        int src = (lane < m) ? g_srcs[base + lane] : 0;
        int j = 0;
        for (; j + 4 <= m; j += 4) {
            int u0 = __shfl_sync(0xffffffffu, src, j + 0);
            int u1 = __shfl_sync(0xffffffffu, src, j + 1);
            int u2 = __shfl_sync(0xffffffffu, src, j + 2);
            int u3 = __shfl_sync(0xffffffffu, src, j + 3);
            float v0 = Sbase[(size_t)u0 * 512 + c];
            float v1 = Sbase[(size_t)u1 * 512 + c];
            float v2 = Sbase[(size_t)u2 * 512 + c];
            float v3 = Sbase[(size_t)u3 * 512 + c];
            acc0 += v0; acc1 += v1; acc2 += v2; acc3 += v3;
        }
        for (; j < m; j++) {
            int u = __shfl_sync(0xffffffffu, src, j);
            acc0 += Sbase[(size_t)u * 512 + c];
        }
    }
    float acc = (acc0 + acc1) + (acc2 + acc3);

    float r = fmaxf(acc, 0.f);
    if (do_bn) {
        r = (r - rm[c]) * rsqrtf(rv[c] + EPSV) * gg[c] + beta[c];
        r = fmaxf(r, 0.f);
    }
    float* o = outp ? outp : g_z;
    o[(size_t)v * FOUT + c] = r;
}

// ---------------- launch -----------------------------------------------------
extern "C" void kernel_launch(void* const* d_in, const int* in_sizes, int n_in,
                              void* d_out, int out_size) {
    const float* x   = (const float*)d_in[0];
    const int*   ei  = (const int*)d_in[1];
    const float* ea  = (const float*)d_in[2];
    const float* W[3] = {(const float*)d_in[3], (const float*)d_in[5], (const float*)d_in[7]};
    const float* b[3] = {(const float*)d_in[4], (const float*)d_in[6], (const float*)d_in[8]};
    const float* g0 = (const float*)d_in[9];
    const float* be0 = (const float*)d_in[10];
    const float* rm0 = (const float*)d_in[11];
    const float* rv0 = (const float*)d_in[12];
    const float* g1 = (const float*)d_in[13];
    const float* be1 = (const float*)d_in[14];
    const float* rm1 = (const float*)d_in[15];
    const float* rv1 = (const float*)d_in[16];
    float* outp = (float*)d_out;

    const int E = in_sizes[1] / 2;
    const int M = NNODES;

    detect_zero_kernel<<<(NNODES + 255) / 256, 256>>>(ei);
    hist_kernel<<<(E + 255) / 256, 256>>>(ei, E);
    scan_kernel<<<1, 1024>>>(M);
    fill_kernel<<<(E + 255) / 256, 256>>>(ei, E);
    ea_kernel<<<(NNODES * 32 + 255) / 256, 256>>>(ea);

    for (int layer = 0; layer < 3; layer++) {
        int K = (layer == 0) ? 128 : 256;
        const float* Xp = (layer == 0) ? x : nullptr;
        int packTotal = 512 * K + FOUT * FEA;
        pack_kernel<<<(packTotal + 255) / 256, 256>>>(W[layer], K);
        c1_kernel<<<1, 256>>>();
        wea_kernel<<<NNODES / 8, 256>>>();
        dim3 grid((M + 127) / 128, 512 / 128);
        tgemm512<<<grid, 256>>>(Xp, M, K);
        if (layer == 0)
            agg_kernel<<<M, 256>>>(b[0], g0, be0, rm0, rv0, nullptr, 1);
        else if (layer == 1)
            agg_kernel<<<M, 256>>>(b[1], g1, be1, rm1, rv1, nullptr, 1);
        else
            agg_kernel<<<M, 256>>>(b[2], nullptr, nullptr, nullptr, nullptr, outp, 0);
    }
}

// round 10
// speedup vs baseline: 3.0229x; 1.0336x over previous
#include <cuda_runtime.h>
#include <cuda_bf16.h>
#include <cstdint>

#define NNODES 20000
#define NEDGES 320000
#define FEA    16
#define FOUT   256
#define EPSV   1e-5f

// ---------------- scratch (static __device__ — no allocation allowed) -------
__device__ int   g_is64;
__device__ int   g_deg[NNODES];
__device__ int   g_rowptr[NNODES + 1];
__device__ int   g_cursor[NNODES];
__device__ int   g_srcs[NEDGES];
__device__ int   g_eids[NEDGES];
__device__ float g_EA[NNODES * FEA];       // per-node summed edge_attr (layer-invariant)
__device__ float g_WEA[NNODES * FOUT];     // per-layer We @ (EA[v] + 1)  (c1 folded in)
__device__ float g_T[NNODES * 512];        // [A | S] per node
__device__ float g_z[NNODES * FOUT];       // inter-layer activations
__device__ float g_V[512 * 256];           // packed [Wd; Ws]
__device__ float g_WeT[FEA * FOUT];        // [k][c]  (coalesced per-channel reads)

__device__ __forceinline__ int edge_val(const int* ei, int E, int which, int e) {
    if (g_is64) return ei[2 * (which * E + e)];
    return ei[which * E + e];
}

__device__ __forceinline__ uint32_t f2tf32(float v) {
    uint32_t t;
    asm("cvt.rna.tf32.f32 %0, %1;" : "=r"(t) : "f"(v));
    return t;
}

// ---------------- dtype detect + init ---------------------------------------
__global__ void detect_zero_kernel(const int* __restrict__ ei) {
    int i = blockIdx.x * blockDim.x + threadIdx.x;
    if (i < NNODES) g_deg[i] = 0;
    if (blockIdx.x == 0 && threadIdx.x == 0) {
        int all0 = 1;
        for (int k = 1; k < 128; k += 2)
            if (ei[k] != 0) { all0 = 0; break; }
        g_is64 = all0;
    }
}

__global__ void hist_kernel(const int* __restrict__ ei, int E) {
    int e = blockIdx.x * blockDim.x + threadIdx.x;
    if (e < E) {
        int d = edge_val(ei, E, 1, e);
        atomicAdd(&g_deg[d], 1);
    }
}

__global__ void scan_kernel(int n) {
    __shared__ int sh[1024];
    __shared__ int carry;
    int tid = threadIdx.x;
    if (tid == 0) { carry = 0; g_rowptr[0] = 0; }
    __syncthreads();
    for (int base = 0; base < n; base += 1024) {
        int i = base + tid;
        int val = (i < n) ? g_deg[i] : 0;
        sh[tid] = val;
        __syncthreads();
        for (int off = 1; off < 1024; off <<= 1) {
            int t = (tid >= off) ? sh[tid - off] : 0;
            __syncthreads();
            sh[tid] += t;
            __syncthreads();
        }
        if (i < n) {
            int incl = carry + sh[tid];
            g_rowptr[i + 1] = incl;
            g_cursor[i] = incl - val;
        }
        __syncthreads();
        if (tid == 1023) carry += sh[1023];
        __syncthreads();
    }
}

__global__ void fill_kernel(const int* __restrict__ ei, int E) {
    int e = blockIdx.x * blockDim.x + threadIdx.x;
    if (e < E) {
        int s = edge_val(ei, E, 0, e);
        int d = edge_val(ei, E, 1, e);
        int pos = atomicAdd(&g_cursor[d], 1);
        g_srcs[pos] = s;
        g_eids[pos] = e;
    }
}

// EA[v][k] = sum over incoming edges of ea[e][k]. One warp per node.
__global__ void ea_kernel(const float* __restrict__ ea) {
    int warp = (blockIdx.x * blockDim.x + threadIdx.x) >> 5;
    if (warp >= NNODES) return;
    int lane = threadIdx.x & 31;
    int j = lane >> 4, k = lane & 15;
    int start = g_rowptr[warp];
    int end   = g_rowptr[warp + 1];
    float acc = 0.f;
    for (int b = start + j; b < end; b += 2) {
        int e = g_eids[b];
        acc += ea[e * FEA + k];
    }
    acc += __shfl_down_sync(0xffffffffu, acc, 16);
    if (lane < 16) g_EA[warp * FEA + k] = acc;
}

// ---------------- per-layer weight pack -------------------------------------
__global__ void pack_kernel(const float* __restrict__ W, int K) {
    int ldw = 2 * K + FEA;
    int total = 512 * K + FOUT * FEA;
    for (int idx = blockIdx.x * blockDim.x + threadIdx.x; idx < total;
         idx += gridDim.x * blockDim.x) {
        if (idx < 512 * K) {
            int j = idx / K, k = idx - j * K;
            int row = j & 255;
            int off = (j >= 256) ? K : 0;
            g_V[idx] = W[row * ldw + off + k];
        } else {
            int i2 = idx - 512 * K;
            int c = i2 >> 4, k = i2 & 15;
            g_WeT[k * FOUT + c] = W[c * ldw + 2 * K + k];
        }
    }
}

// WEA[v][c] = dot(We[c], EA[v] + 1)   (the +1 folds in the self-loop c1 term)
__global__ __launch_bounds__(256) void wea_kernel() {
    __shared__ float sEA[8][FEA + 1];
    int tid = threadIdx.x;
    int v0 = blockIdx.x * 8;
    if (tid < 8 * FEA) sEA[tid >> 4][tid & 15] = g_EA[v0 * FEA + tid] + 1.0f;
    __syncthreads();
    float wec[FEA];
#pragma unroll
    for (int k = 0; k < FEA; k++) wec[k] = g_WeT[k * FOUT + tid];
#pragma unroll
    for (int j = 0; j < 8; j++) {
        float d = 0.f;
#pragma unroll
        for (int k = 0; k < FEA; k++) d = fmaf(wec[k], sEA[j][k], d);
        g_WEA[(size_t)(v0 + j) * FOUT + tid] = d;
    }
}

// ---------------- TF32 tensor-core GEMM: T[M x 512] = X[M x K] * g_V^T -------
// 128x128 block tile, BK=16, double-buffered smem, 8 warps (2x4), m16n8k8.
#define SM_STRIDE 132
__global__ __launch_bounds__(256, 2) void tgemm512(const float* __restrict__ Xin,
                                                   int M, int K) {
    const float* X = Xin ? Xin : g_z;
    constexpr int BM = 128, BK = 16;
    __shared__ uint32_t As[2][BK][SM_STRIDE];
    __shared__ uint32_t Bs[2][BK][SM_STRIDE];
    int tid  = threadIdx.x;
    int lane = tid & 31;
    int warp = tid >> 5;
    int gid  = lane >> 2;
    int tig  = lane & 3;
    int warpM = warp >> 2;
    int warpN = warp & 3;
    int m0 = blockIdx.x * BM;
    int n0 = blockIdx.y * BM;

    // staging layout: idx = tid + j*256, j=0..1 ; r = idx>>2, c4 = (idx&3)*4
    int r_st  = tid >> 2;            // 0..63  (+64 for j=1)
    int c4_st = (tid & 3) * 4;

    float acc[4][4][4];
#pragma unroll
    for (int mt = 0; mt < 4; mt++)
#pragma unroll
        for (int nt = 0; nt < 4; nt++)
#pragma unroll
            for (int f = 0; f < 4; f++) acc[mt][nt][f] = 0.f;

    int nStages = K / BK;

    // prologue: stage 0
    {
#pragma unroll
        for (int j = 0; j < 2; j++) {
            int r = r_st + j * 64;
            int gr = m0 + r;
            float4 va = (gr < M) ? *(const float4*)&X[(size_t)gr * K + c4_st]
                                 : make_float4(0.f, 0.f, 0.f, 0.f);
            As[0][c4_st + 0][r] = f2tf32(va.x);
            As[0][c4_st + 1][r] = f2tf32(va.y);
            As[0][c4_st + 2][r] = f2tf32(va.z);
            As[0][c4_st + 3][r] = f2tf32(va.w);
            float4 vb = *(const float4*)&g_V[(size_t)(n0 + r) * K + c4_st];
            Bs[0][c4_st + 0][r] = f2tf32(vb.x);
            Bs[0][c4_st + 1][r] = f2tf32(vb.y);
            Bs[0][c4_st + 2][r] = f2tf32(vb.z);
            Bs[0][c4_st + 3][r] = f2tf32(vb.w);
        }
    }
    __syncthreads();

    for (int s = 0; s < nStages; s++) {
        int buf = s & 1;
        float4 pa[2], pb[2];
        bool hasNext = (s + 1) < nStages;
        if (hasNext) {
            int k0 = (s + 1) * BK;
#pragma unroll
            for (int j = 0; j < 2; j++) {
                int r = r_st + j * 64;
                int gr = m0 + r;
                pa[j] = (gr < M) ? *(const float4*)&X[(size_t)gr * K + k0 + c4_st]
                                 : make_float4(0.f, 0.f, 0.f, 0.f);
                pb[j] = *(const float4*)&g_V[(size_t)(n0 + r) * K + k0 + c4_st];
            }
        }

#pragma unroll
        for (int ks = 0; ks < BK; ks += 8) {
            uint32_t a[4][4];
#pragma unroll
            for (int mt = 0; mt < 4; mt++) {
                int m = warpM * 64 + mt * 16 + gid;
                a[mt][0] = As[buf][ks + tig][m];
                a[mt][1] = As[buf][ks + tig][m + 8];
                a[mt][2] = As[buf][ks + tig + 4][m];
                a[mt][3] = As[buf][ks + tig + 4][m + 8];
            }
            uint32_t b[4][2];
#pragma unroll
            for (int nt = 0; nt < 4; nt++) {
                int n = warpN * 32 + nt * 8 + gid;
                b[nt][0] = Bs[buf][ks + tig][n];
                b[nt][1] = Bs[buf][ks + tig + 4][n];
            }
#pragma unroll
            for (int mt = 0; mt < 4; mt++)
#pragma unroll
                for (int nt = 0; nt < 4; nt++) {
                    asm volatile(
                        "mma.sync.aligned.m16n8k8.row.col.f32.tf32.tf32.f32 "
                        "{%0,%1,%2,%3}, {%4,%5,%6,%7}, {%8,%9}, {%0,%1,%2,%3};"
                        : "+f"(acc[mt][nt][0]), "+f"(acc[mt][nt][1]),
                          "+f"(acc[mt][nt][2]), "+f"(acc[mt][nt][3])
                        : "r"(a[mt][0]), "r"(a[mt][1]), "r"(a[mt][2]), "r"(a[mt][3]),
                          "r"(b[nt][0]), "r"(b[nt][1]));
                }
        }

        if (hasNext) {
            int nbuf = buf ^ 1;
#pragma unroll
            for (int j = 0; j < 2; j++) {
                int r = r_st + j * 64;
                As[nbuf][c4_st + 0][r] = f2tf32(pa[j].x);
                As[nbuf][c4_st + 1][r] = f2tf32(pa[j].y);
                As[nbuf][c4_st + 2][r] = f2tf32(pa[j].z);
                As[nbuf][c4_st + 3][r] = f2tf32(pa[j].w);
                Bs[nbuf][c4_st + 0][r] = f2tf32(pb[j].x);
                Bs[nbuf][c4_st + 1][r] = f2tf32(pb[j].y);
                Bs[nbuf][c4_st + 2][r] = f2tf32(pb[j].z);
                Bs[nbuf][c4_st + 3][r] = f2tf32(pb[j].w);
            }
        }
        __syncthreads();
    }

#pragma unroll
    for (int mt = 0; mt < 4; mt++) {
        int r0 = m0 + warpM * 64 + mt * 16 + gid;
        int r1 = r0 + 8;
#pragma unroll
        for (int nt = 0; nt < 4; nt++) {
            int col = n0 + warpN * 32 + nt * 8 + tig * 2;
            if (r0 < M)
                *(float2*)&g_T[(size_t)r0 * 512 + col] =
                    make_float2(acc[mt][nt][0], acc[mt][nt][1]);
            if (r1 < M)
                *(float2*)&g_T[(size_t)r1 * 512 + col] =
                    make_float2(acc[mt][nt][2], acc[mt][nt][3]);
        }
    }
}

// ---------------- aggregation + epilogue ------------------------------------
// acc = (deg+1)*(A[v]+b) + S[v] + WEA[v][c] + sum_{e->v} S[src_e]
__global__ __launch_bounds__(256) void agg_kernel(const float* __restrict__ bias,
                           const float* __restrict__ gg,
                           const float* __restrict__ beta,
                           const float* __restrict__ rm,
                           const float* __restrict__ rv,
                           float* __restrict__ outp, int do_bn) {
    int v = blockIdx.x;
    int c = threadIdx.x;
    int lane = c & 31;

    int start = g_rowptr[v];
    int end   = g_rowptr[v + 1];
    float a = g_T[(size_t)v * 512 + c];
    float s = g_T[(size_t)v * 512 + 256 + c];
    float dot = g_WEA[(size_t)v * FOUT + c];
    float acc0 = (float)(end - start + 1) * (a + bias[c]) + s + dot;
    float acc1 = 0.f, acc2 = 0.f, acc3 = 0.f;

    const float* Sbase = &g_T[256];
    for (int base = start; base < end; base += 32) {
        int m = end - base;
        if (m > 32) m = 32;
        int src = (lane < m) ? g_srcs[base + lane] : 0;
        int j = 0;
        for (; j + 4 <= m; j += 4) {
            int u0 = __shfl_sync(0xffffffffu, src, j + 0);
            int u1 = __shfl_sync(0xffffffffu, src, j + 1);
            int u2 = __shfl_sync(0xffffffffu, src, j + 2);
            int u3 = __shfl_sync(0xffffffffu, src, j + 3);
            float v0 = Sbase[(size_t)u0 * 512 + c];
            float v1 = Sbase[(size_t)u1 * 512 + c];
            float v2 = Sbase[(size_t)u2 * 512 + c];
            float v3 = Sbase[(size_t)u3 * 512 + c];
            acc0 += v0; acc1 += v1; acc2 += v2; acc3 += v3;
        }
        for (; j < m; j++) {
            int u = __shfl_sync(0xffffffffu, src, j);
            acc0 += Sbase[(size_t)u * 512 + c];
        }
    }
    float acc = (acc0 + acc1) + (acc2 + acc3);

    float r = fmaxf(acc, 0.f);
    if (do_bn) {
        r = (r - rm[c]) * rsqrtf(rv[c] + EPSV) * gg[c] + beta[c];
        r = fmaxf(r, 0.f);
    }
    float* o = outp ? outp : g_z;
    o[(size_t)v * FOUT + c] = r;
}

// ---------------- launch -----------------------------------------------------
extern "C" void kernel_launch(void* const* d_in, const int* in_sizes, int n_in,
                              void* d_out, int out_size) {
    const float* x   = (const float*)d_in[0];
    const int*   ei  = (const int*)d_in[1];
    const float* ea  = (const float*)d_in[2];
    const float* W[3] = {(const float*)d_in[3], (const float*)d_in[5], (const float*)d_in[7]};
    const float* b[3] = {(const float*)d_in[4], (const float*)d_in[6], (const float*)d_in[8]};
    const float* g0 = (const float*)d_in[9];
    const float* be0 = (const float*)d_in[10];
    const float* rm0 = (const float*)d_in[11];
    const float* rv0 = (const float*)d_in[12];
    const float* g1 = (const float*)d_in[13];
    const float* be1 = (const float*)d_in[14];
    const float* rm1 = (const float*)d_in[15];
    const float* rv1 = (const float*)d_in[16];
    float* outp = (float*)d_out;

    const int E = in_sizes[1] / 2;
    const int M = NNODES;

    detect_zero_kernel<<<(NNODES + 255) / 256, 256>>>(ei);
    hist_kernel<<<(E + 255) / 256, 256>>>(ei, E);
    scan_kernel<<<1, 1024>>>(M);
    fill_kernel<<<(E + 255) / 256, 256>>>(ei, E);
    ea_kernel<<<(NNODES * 32 + 255) / 256, 256>>>(ea);

    for (int layer = 0; layer < 3; layer++) {
        int K = (layer == 0) ? 128 : 256;
        const float* Xp = (layer == 0) ? x : nullptr;
        int packTotal = 512 * K + FOUT * FEA;
        pack_kernel<<<(packTotal + 255) / 256, 256>>>(W[layer], K);
        wea_kernel<<<NNODES / 8, 256>>>();
        dim3 grid((M + 127) / 128, 512 / 128);
        tgemm512<<<grid, 256>>>(Xp, M, K);
        if (layer == 0)
            agg_kernel<<<M, 256>>>(b[0], g0, be0, rm0, rv0, nullptr, 1);
        else if (layer == 1)
            agg_kernel<<<M, 256>>>(b[1], g1, be1, rm1, rv1, nullptr, 1);
        else
            agg_kernel<<<M, 256>>>(b[2], nullptr, nullptr, nullptr, nullptr, outp, 0);
    }
}

// round 12
// speedup vs baseline: 3.4539x; 1.1426x over previous
#include <cuda_runtime.h>
#include <cuda_bf16.h>
#include <cstdint>

#define NNODES 20000
#define NEDGES 320000
#define FEA    16
#define FOUT   256
#define EPSV   1e-5f

// ---------------- scratch (static __device__ — no allocation allowed) -------
__device__ int   g_is64;
__device__ int   g_ctr;
__device__ int   g_deg[NNODES];
__device__ int   g_rowstart[NNODES];
__device__ int   g_cursor[NNODES];
__device__ int   g_srcs[NEDGES];
__device__ int   g_eids[NEDGES];
__device__ float g_EA[NNODES * FEA];       // per-node summed edge_attr (layer-invariant)
__device__ float g_WEA[NNODES * FOUT];     // per-layer We @ (EA[v] + 1)
__device__ float g_T[NNODES * 512];        // [A | S] per node
__device__ float g_z[NNODES * FOUT];       // inter-layer activations
__device__ float g_V[512 * 256];           // packed [Wd; Ws]
__device__ float g_WeT[FEA * FOUT];        // [k][c]

__device__ __forceinline__ int edge_val(const int* ei, int E, int which, int e) {
    if (g_is64) return ei[2 * (which * E + e)];
    return ei[which * E + e];
}

__device__ __forceinline__ uint32_t f2tf32(float v) {
    uint32_t t;
    asm("cvt.rna.tf32.f32 %0, %1;" : "=r"(t) : "f"(v));
    return t;
}

// ---------------- dtype detect + init ---------------------------------------
__global__ void detect_zero_kernel(const int* __restrict__ ei) {
    int i = blockIdx.x * blockDim.x + threadIdx.x;
    if (i < NNODES) g_deg[i] = 0;
    if (blockIdx.x == 0 && threadIdx.x == 0) {
        int all0 = 1;
        for (int k = 1; k < 128; k += 2)
            if (ei[k] != 0) { all0 = 0; break; }
        g_is64 = all0;
        g_ctr = 0;
    }
}

__global__ void hist_kernel(const int* __restrict__ ei, int E) {
    int e = blockIdx.x * blockDim.x + threadIdx.x;
    if (e < E) {
        int d = edge_val(ei, E, 1, e);
        atomicAdd(&g_deg[d], 1);
    }
}

// Parallel bucket allocation: block scan + one atomicAdd per block.
// Bucket placement order is arbitrary but each node gets a unique contiguous range.
__global__ void alloc_kernel() {
    int tid = threadIdx.x;
    int i = blockIdx.x * 256 + tid;
    int lane = tid & 31, wid = tid >> 5;
    int d = (i < NNODES) ? g_deg[i] : 0;
    int v = d;
#pragma unroll
    for (int o = 1; o < 32; o <<= 1) {
        int t = __shfl_up_sync(0xffffffffu, v, o);
        if (lane >= o) v += t;
    }
    __shared__ int wsum[8];
    __shared__ int blockbase;
    if (lane == 31) wsum[wid] = v;
    __syncthreads();
    if (wid == 0) {
        int s = (lane < 8) ? wsum[lane] : 0;
#pragma unroll
        for (int o = 1; o < 8; o <<= 1) {
            int t = __shfl_up_sync(0xffffffffu, s, o);
            if (lane >= o) s += t;
        }
        if (lane < 8) wsum[lane] = s;
        if (lane == 7) blockbase = atomicAdd(&g_ctr, s);
    }
    __syncthreads();
    int excl = v - d + (wid ? wsum[wid - 1] : 0);
    if (i < NNODES) {
        int st = blockbase + excl;
        g_rowstart[i] = st;
        g_cursor[i] = st;
    }
}

__global__ void fill_kernel(const int* __restrict__ ei, int E) {
    int e = blockIdx.x * blockDim.x + threadIdx.x;
    if (e < E) {
        int s = edge_val(ei, E, 0, e);
        int d = edge_val(ei, E, 1, e);
        int pos = atomicAdd(&g_cursor[d], 1);
        g_srcs[pos] = s;
        g_eids[pos] = e;
    }
}

// EA[v][k] = sum over incoming edges of ea[e][k]. One warp per node.
__global__ void ea_kernel(const float* __restrict__ ea) {
    int warp = (blockIdx.x * blockDim.x + threadIdx.x) >> 5;
    if (warp >= NNODES) return;
    int lane = threadIdx.x & 31;
    int j = lane >> 4, k = lane & 15;
    int start = g_rowstart[warp];
    int end   = start + g_deg[warp];
    float acc = 0.f;
    for (int b = start + j; b < end; b += 2) {
        int e = g_eids[b];
        acc += ea[e * FEA + k];
    }
    acc += __shfl_down_sync(0xffffffffu, acc, 16);
    if (lane < 16) g_EA[warp * FEA + k] = acc;
}

// ---------------- per-layer weight pack -------------------------------------
__global__ void pack_kernel(const float* __restrict__ W, int K) {
    int ldw = 2 * K + FEA;
    int total = 512 * K + FOUT * FEA;
    for (int idx = blockIdx.x * blockDim.x + threadIdx.x; idx < total;
         idx += gridDim.x * blockDim.x) {
        if (idx < 512 * K) {
            int j = idx / K, k = idx - j * K;
            int row = j & 255;
            int off = (j >= 256) ? K : 0;
            g_V[idx] = W[row * ldw + off + k];
        } else {
            int i2 = idx - 512 * K;
            int c = i2 >> 4, k = i2 & 15;
            g_WeT[k * FOUT + c] = W[c * ldw + 2 * K + k];
        }
    }
}

// WEA[v][c] = dot(We[c], EA[v] + 1)
__global__ __launch_bounds__(256) void wea_kernel() {
    __shared__ float sEA[8][FEA + 1];
    int tid = threadIdx.x;
    int v0 = blockIdx.x * 8;
    if (tid < 8 * FEA) sEA[tid >> 4][tid & 15] = g_EA[v0 * FEA + tid] + 1.0f;
    __syncthreads();
    float wec[FEA];
#pragma unroll
    for (int k = 0; k < FEA; k++) wec[k] = g_WeT[k * FOUT + tid];
#pragma unroll
    for (int j = 0; j < 8; j++) {
        float d = 0.f;
#pragma unroll
        for (int k = 0; k < FEA; k++) d = fmaf(wec[k], sEA[j][k], d);
        g_WEA[(size_t)(v0 + j) * FOUT + tid] = d;
    }
}

// ---------------- TF32 tensor-core GEMM: T[M x 512] = X[M x K] * g_V^T -------
// 128x128 tile, BK=16, double-buffered, k-paired smem (uint2) for LDS.64 frags.
#define SM_STRIDE 132
__global__ __launch_bounds__(256, 2) void tgemm512(const float* __restrict__ Xin,
                                                   int M, int K) {
    const float* X = Xin ? Xin : g_z;
    constexpr int BM = 128, BK = 16;
    // AsP[buf][kp][m] : uint2 = (tf32 at k, tf32 at k+4); kp = (k&3) + 4*(k>>3)
    __shared__ uint2 AsP[2][8][SM_STRIDE];
    __shared__ uint2 BsP[2][8][SM_STRIDE];
    int tid  = threadIdx.x;
    int lane = tid & 31;
    int warp = tid >> 5;
    int gid  = lane >> 2;
    int tig  = lane & 3;
    int warpM = warp >> 2;
    int warpN = warp & 3;
    int m0 = blockIdx.x * BM;
    int n0 = blockIdx.y * BM;

    // staging: thread covers rows r_st, r_st+64 at k cols c4_st..c4_st+3
    int r_st  = tid >> 2;
    int c4_st = (tid & 3) * 4;
    int kp0   = (c4_st & 8) >> 1;        // 0 or 4
    int hh    = (c4_st >> 2) & 1;        // 0 -> .x, 1 -> .y

    float acc[4][4][4];
#pragma unroll
    for (int mt = 0; mt < 4; mt++)
#pragma unroll
        for (int nt = 0; nt < 4; nt++)
#pragma unroll
            for (int f = 0; f < 4; f++) acc[mt][nt][f] = 0.f;

    int nStages = K / BK;

#define STAGE(buf_, pa0, pa1, pb0, pb1)                                        \
    {                                                                          \
        uint32_t* Aw = (uint32_t*)&AsP[buf_][0][0];                            \
        uint32_t* Bw = (uint32_t*)&BsP[buf_][0][0];                            \
        float4 _va[2] = {pa0, pa1};                                            \
        float4 _vb[2] = {pb0, pb1};                                            \
        _Pragma("unroll")                                                      \
        for (int j = 0; j < 2; j++) {                                          \
            int r = r_st + j * 64;                                             \
            float* fa = (float*)&_va[j];                                       \
            float* fb = (float*)&_vb[j];                                       \
            _Pragma("unroll")                                                  \
            for (int q = 0; q < 4; q++) {                                      \
                int w = ((kp0 + q) * SM_STRIDE + r) * 2 + hh;                  \
                Aw[w] = f2tf32(fa[q]);                                         \
                Bw[w] = f2tf32(fb[q]);                                         \
            }                                                                  \
        }                                                                      \
    }

    // prologue: stage 0
    {
        float4 pa[2], pb[2];
#pragma unroll
        for (int j = 0; j < 2; j++) {
            int r = r_st + j * 64;
            int gr = m0 + r;
            pa[j] = (gr < M) ? *(const float4*)&X[(size_t)gr * K + c4_st]
                             : make_float4(0.f, 0.f, 0.f, 0.f);
            pb[j] = *(const float4*)&g_V[(size_t)(n0 + r) * K + c4_st];
        }
        STAGE(0, pa[0], pa[1], pb[0], pb[1]);
    }
    __syncthreads();

    for (int s = 0; s < nStages; s++) {
        int buf = s & 1;
        float4 pa[2], pb[2];
        bool hasNext = (s + 1) < nStages;
        if (hasNext) {
            int k0 = (s + 1) * BK;
#pragma unroll
            for (int j = 0; j < 2; j++) {
                int r = r_st + j * 64;
                int gr = m0 + r;
                pa[j] = (gr < M) ? *(const float4*)&X[(size_t)gr * K + k0 + c4_st]
                                 : make_float4(0.f, 0.f, 0.f, 0.f);
                pb[j] = *(const float4*)&g_V[(size_t)(n0 + r) * K + k0 + c4_st];
            }
        }

#pragma unroll
        for (int ks = 0; ks < BK; ks += 8) {
            int kp = tig + ((ks >> 3) << 2);
            uint32_t a[4][4];
#pragma unroll
            for (int mt = 0; mt < 4; mt++) {
                int m = warpM * 64 + mt * 16 + gid;
                uint2 vm  = AsP[buf][kp][m];
                uint2 vm8 = AsP[buf][kp][m + 8];
                a[mt][0] = vm.x;  a[mt][1] = vm8.x;
                a[mt][2] = vm.y;  a[mt][3] = vm8.y;
            }
            uint32_t b[4][2];
#pragma unroll
            for (int nt = 0; nt < 4; nt++) {
                int n = warpN * 32 + nt * 8 + gid;
                uint2 vn = BsP[buf][kp][n];
                b[nt][0] = vn.x;  b[nt][1] = vn.y;
            }
#pragma unroll
            for (int mt = 0; mt < 4; mt++)
#pragma unroll
                for (int nt = 0; nt < 4; nt++) {
                    asm volatile(
                        "mma.sync.aligned.m16n8k8.row.col.f32.tf32.tf32.f32 "
                        "{%0,%1,%2,%3}, {%4,%5,%6,%7}, {%8,%9}, {%0,%1,%2,%3};"
                        : "+f"(acc[mt][nt][0]), "+f"(acc[mt][nt][1]),
                          "+f"(acc[mt][nt][2]), "+f"(acc[mt][nt][3])
                        : "r"(a[mt][0]), "r"(a[mt][1]), "r"(a[mt][2]), "r"(a[mt][3]),
                          "r"(b[nt][0]), "r"(b[nt][1]));
                }
        }

        if (hasNext) {
            STAGE(buf ^ 1, pa[0], pa[1], pb[0], pb[1]);
        }
        __syncthreads();
    }
#undef STAGE

#pragma unroll
    for (int mt = 0; mt < 4; mt++) {
        int r0 = m0 + warpM * 64 + mt * 16 + gid;
        int r1 = r0 + 8;
#pragma unroll
        for (int nt = 0; nt < 4; nt++) {
            int col = n0 + warpN * 32 + nt * 8 + tig * 2;
            if (r0 < M)
                *(float2*)&g_T[(size_t)r0 * 512 + col] =
                    make_float2(acc[mt][nt][0], acc[mt][nt][1]);
            if (r1 < M)
                *(float2*)&g_T[(size_t)r1 * 512 + col] =
                    make_float2(acc[mt][nt][2], acc[mt][nt][3]);
        }
    }
}

// ---------------- aggregation + epilogue ------------------------------------
// acc = (deg+1)*(A[v]+b) + S[v] + WEA[v][c] + sum_{e->v} S[src_e]
__global__ __launch_bounds__(256) void agg_kernel(const float* __restrict__ bias,
                           const float* __restrict__ gg,
                           const float* __restrict__ beta,
                           const float* __restrict__ rm,
                           const float* __restrict__ rv,
                           float* __restrict__ outp, int do_bn) {
    int v = blockIdx.x;
    int c = threadIdx.x;
    int lane = c & 31;

    int start = g_rowstart[v];
    int end   = start + g_deg[v];
    float a = g_T[(size_t)v * 512 + c];
    float s = g_T[(size_t)v * 512 + 256 + c];
    float dot = g_WEA[(size_t)v * FOUT + c];
    float acc0 = (float)(end - start + 1) * (a + bias[c]) + s + dot;
    float acc1 = 0.f, acc2 = 0.f, acc3 = 0.f;

    const float* Sbase = &g_T[256];
    for (int base = start; base < end; base += 32) {
        int m = end - base;
        if (m > 32) m = 32;
        int src = (lane < m) ? g_srcs[base + lane] : 0;
        int j = 0;
        for (; j + 4 <= m; j += 4) {
            int u0 = __shfl_sync(0xffffffffu, src, j + 0);
            int u1 = __shfl_sync(0xffffffffu, src, j + 1);
            int u2 = __shfl_sync(0xffffffffu, src, j + 2);
            int u3 = __shfl_sync(0xffffffffu, src, j + 3);
            float v0 = Sbase[(size_t)u0 * 512 + c];
            float v1 = Sbase[(size_t)u1 * 512 + c];
            float v2 = Sbase[(size_t)u2 * 512 + c];
            float v3 = Sbase[(size_t)u3 * 512 + c];
            acc0 += v0; acc1 += v1; acc2 += v2; acc3 += v3;
        }
        for (; j < m; j++) {
            int u = __shfl_sync(0xffffffffu, src, j);
            acc0 += Sbase[(size_t)u * 512 + c];
        }
    }
    float acc = (acc0 + acc1) + (acc2 + acc3);

    float r = fmaxf(acc, 0.f);
    if (do_bn) {
        r = (r - rm[c]) * rsqrtf(rv[c] + EPSV) * gg[c] + beta[c];
        r = fmaxf(r, 0.f);
    }
    float* o = outp ? outp : g_z;
    o[(size_t)v * FOUT + c] = r;
}

// ---------------- launch -----------------------------------------------------
extern "C" void kernel_launch(void* const* d_in, const int* in_sizes, int n_in,
                              void* d_out, int out_size) {
    const float* x   = (const float*)d_in[0];
    const int*   ei  = (const int*)d_in[1];
    const float* ea  = (const float*)d_in[2];
    const float* W[3] = {(const float*)d_in[3], (const float*)d_in[5], (const float*)d_in[7]};
    const float* b[3] = {(const float*)d_in[4], (const float*)d_in[6], (const float*)d_in[8]};
    const float* g0 = (const float*)d_in[9];
    const float* be0 = (const float*)d_in[10];
    const float* rm0 = (const float*)d_in[11];
    const float* rv0 = (const float*)d_in[12];
    const float* g1 = (const float*)d_in[13];
    const float* be1 = (const float*)d_in[14];
    const float* rm1 = (const float*)d_in[15];
    const float* rv1 = (const float*)d_in[16];
    float* outp = (float*)d_out;

    const int E = in_sizes[1] / 2;
    const int M = NNODES;

    detect_zero_kernel<<<(NNODES + 255) / 256, 256>>>(ei);
    hist_kernel<<<(E + 255) / 256, 256>>>(ei, E);
    alloc_kernel<<<(NNODES + 255) / 256, 256>>>();
    fill_kernel<<<(E + 255) / 256, 256>>>(ei, E);
    ea_kernel<<<(NNODES * 32 + 255) / 256, 256>>>(ea);

    for (int layer = 0; layer < 3; layer++) {
        int K = (layer == 0) ? 128 : 256;
        const float* Xp = (layer == 0) ? x : nullptr;
        int packTotal = 512 * K + FOUT * FEA;
        pack_kernel<<<(packTotal + 255) / 256, 256>>>(W[layer], K);
        wea_kernel<<<NNODES / 8, 256>>>();
        dim3 grid((M + 127) / 128, 512 / 128);
        tgemm512<<<grid, 256>>>(Xp, M, K);
        if (layer == 0)
            agg_kernel<<<M, 256>>>(b[0], g0, be0, rm0, rv0, nullptr, 1);
        else if (layer == 1)
            agg_kernel<<<M, 256>>>(b[1], g1, be1, rm1, rv1, nullptr, 1);
        else
            agg_kernel<<<M, 256>>>(b[2], nullptr, nullptr, nullptr, nullptr, outp, 0);
    }
}

// round 16
// speedup vs baseline: 3.4734x; 1.0057x over previous
#include <cuda_runtime.h>
#include <cuda_bf16.h>
#include <cstdint>

#define NNODES 20000
#define NEDGES 320000
#define FEA    16
#define FOUT   256
#define EPSV   1e-5f

// ---------------- scratch (static __device__ — no allocation allowed) -------
// All __device__ symbols are referenced ONLY from device code (host-side use of
// these symbols is UB and trips the harness memory guard).
__device__ int      g_is64;
__device__ int      g_ctr;
__device__ int      g_deg[NNODES];
__device__ int      g_rowstart[NNODES];
__device__ int      g_cursor[NNODES];
__device__ int      g_srcs[NEDGES];
__device__ int      g_eids[NEDGES];
__device__ float    g_EA[NNODES * FEA];        // per-node summed edge_attr
__device__ float    g_WEA[NNODES * FOUT];      // current layer's We @ (EA[v] + 1)
__device__ float    g_T[NNODES * 512];         // [A | S] per node (fp32)
__device__ uint32_t g_z[NNODES * FOUT];        // tf32 bits: x (layer 0) / activations
__device__ uint32_t g_V[3 * 512 * 256];        // packed [Wd; Ws] (tf32 bits), per layer
__device__ float    g_WeT[3 * FEA * FOUT];     // [l][k][c]

__device__ __forceinline__ int edge_val(const int* ei, int E, int which, int e) {
    if (g_is64) return ei[2 * (which * E + e)];
    return ei[which * E + e];
}

__device__ __forceinline__ uint32_t f2tf32(float v) {
    uint32_t t;
    asm("cvt.rna.tf32.f32 %0, %1;" : "=r"(t) : "f"(v));
    return t;
}

// ---------------- dtype detect + init ---------------------------------------
__global__ void detect_zero_kernel(const int* __restrict__ ei) {
    int i = blockIdx.x * blockDim.x + threadIdx.x;
    if (i < NNODES) g_deg[i] = 0;
    if (blockIdx.x == 0 && threadIdx.x == 0) {
        int all0 = 1;
        for (int k = 1; k < 128; k += 2)
            if (ei[k] != 0) { all0 = 0; break; }
        g_is64 = all0;
        g_ctr = 0;
    }
}

__global__ void hist_kernel(const int* __restrict__ ei, int E) {
    int e = blockIdx.x * blockDim.x + threadIdx.x;
    if (e < E) {
        int d = edge_val(ei, E, 1, e);
        atomicAdd(&g_deg[d], 1);
    }
}

// Parallel bucket allocation: block scan + one atomicAdd per block.
__global__ void alloc_kernel() {
    int tid = threadIdx.x;
    int i = blockIdx.x * 256 + tid;
    int lane = tid & 31, wid = tid >> 5;
    int d = (i < NNODES) ? g_deg[i] : 0;
    int v = d;
#pragma unroll
    for (int o = 1; o < 32; o <<= 1) {
        int t = __shfl_up_sync(0xffffffffu, v, o);
        if (lane >= o) v += t;
    }
    __shared__ int wsum[8];
    __shared__ int blockbase;
    if (lane == 31) wsum[wid] = v;
    __syncthreads();
    if (wid == 0) {
        int s = (lane < 8) ? wsum[lane] : 0;
#pragma unroll
        for (int o = 1; o < 8; o <<= 1) {
            int t = __shfl_up_sync(0xffffffffu, s, o);
            if (lane >= o) s += t;
        }
        if (lane < 8) wsum[lane] = s;
        if (lane == 7) blockbase = atomicAdd(&g_ctr, s);
    }
    __syncthreads();
    int excl = v - d + (wid ? wsum[wid - 1] : 0);
    if (i < NNODES) {
        int st = blockbase + excl;
        g_rowstart[i] = st;
        g_cursor[i] = st;
    }
}

__global__ void fill_kernel(const int* __restrict__ ei, int E) {
    int e = blockIdx.x * blockDim.x + threadIdx.x;
    if (e < E) {
        int s = edge_val(ei, E, 0, e);
        int d = edge_val(ei, E, 1, e);
        int pos = atomicAdd(&g_cursor[d], 1);
        g_srcs[pos] = s;
        g_eids[pos] = e;
    }
}

// EA[v][k] = sum over incoming edges of ea[e][k]. One warp per node.
__global__ void ea_kernel(const float* __restrict__ ea) {
    int warp = (blockIdx.x * blockDim.x + threadIdx.x) >> 5;
    if (warp >= NNODES) return;
    int lane = threadIdx.x & 31;
    int j = lane >> 4, k = lane & 15;
    int start = g_rowstart[warp];
    int end   = start + g_deg[warp];
    float acc = 0.f;
    for (int b = start + j; b < end; b += 2) {
        int e = g_eids[b];
        acc += ea[e * FEA + k];
    }
    acc += __shfl_down_sync(0xffffffffu, acc, 16);
    if (lane < 16) g_EA[warp * FEA + k] = acc;
}

// Convert x to tf32 bits into g_z (layer-0 GEMM input; later overwritten by agg).
__global__ void xcvt_kernel(const float* __restrict__ x) {
    int i = blockIdx.x * blockDim.x + threadIdx.x;   // float4 index
    if (i < NNODES * 128 / 4) {
        float4 v = *(const float4*)&x[i * 4];
        uint4 u;
        u.x = f2tf32(v.x); u.y = f2tf32(v.y);
        u.z = f2tf32(v.z); u.w = f2tf32(v.w);
        *(uint4*)&g_z[i * 4] = u;
    }
}

// ---------------- all-layer weight pack (tf32 bits) --------------------------
__global__ void pack_all_kernel(const float* __restrict__ W0,
                                const float* __restrict__ W1,
                                const float* __restrict__ W2) {
    int l = blockIdx.y;
    const float* W = (l == 0) ? W0 : (l == 1) ? W1 : W2;
    int K = (l == 0) ? 128 : 256;
    int ldw = 2 * K + FEA;
    int total = 512 * K + FOUT * FEA;
    uint32_t* V = g_V + l * (512 * 256);
    float* WeT = g_WeT + l * (FEA * FOUT);
    for (int idx = blockIdx.x * blockDim.x + threadIdx.x; idx < total;
         idx += gridDim.x * blockDim.x) {
        if (idx < 512 * K) {
            int j = idx / K, k = idx - j * K;
            int row = j & 255;
            int off = (j >= 256) ? K : 0;
            V[idx] = f2tf32(W[row * ldw + off + k]);
        } else {
            int i2 = idx - 512 * K;
            int c = i2 >> 4, k = i2 & 15;
            WeT[k * FOUT + c] = W[c * ldw + 2 * K + k];
        }
    }
}

// WEA[v][c] = dot(We_l[c], EA[v] + 1) for layer l (single reused buffer).
__global__ __launch_bounds__(256) void wea_kernel(int l) {
    __shared__ float sEA[8][FEA + 1];
    int tid = threadIdx.x;
    int v0 = blockIdx.x * 8;
    if (tid < 8 * FEA) sEA[tid >> 4][tid & 15] = g_EA[v0 * FEA + tid] + 1.0f;
    __syncthreads();
    const float* WeT = g_WeT + l * (FEA * FOUT);
    float wec[FEA];
#pragma unroll
    for (int k = 0; k < FEA; k++) wec[k] = WeT[k * FOUT + tid];
#pragma unroll
    for (int j = 0; j < 8; j++) {
        float d = 0.f;
#pragma unroll
        for (int k = 0; k < FEA; k++) d = fmaf(wec[k], sEA[j][k], d);
        g_WEA[(size_t)(v0 + j) * FOUT + tid] = d;
    }
}

// ---------------- TF32 tensor-core GEMM: T[M x 512] = g_z[M x K] * V_l^T -----
// Operands are pre-converted tf32 bits — staging is pure copy, no cvt.
// X and V are resolved from __device__ symbols in device code (layer arg).
#define SM_STRIDE 132
__global__ __launch_bounds__(256, 2) void tgemm512(int layer, int M, int K) {
    const uint32_t* __restrict__ X = g_z;
    const uint32_t* __restrict__ V = g_V + layer * (512 * 256);
    constexpr int BM = 128, BK = 16;
    __shared__ uint2 AsP[2][8][SM_STRIDE];
    __shared__ uint2 BsP[2][8][SM_STRIDE];
    int tid  = threadIdx.x;
    int lane = tid & 31;
    int warp = tid >> 5;
    int gid  = lane >> 2;
    int tig  = lane & 3;
    int warpM = warp >> 2;
    int warpN = warp & 3;
    int m0 = blockIdx.x * BM;
    int n0 = blockIdx.y * BM;

    int r_st  = tid >> 2;
    int c4_st = (tid & 3) * 4;
    int kp0   = (c4_st & 8) >> 1;
    int hh    = (c4_st >> 2) & 1;

    float acc[4][4][4];
#pragma unroll
    for (int mt = 0; mt < 4; mt++)
#pragma unroll
        for (int nt = 0; nt < 4; nt++)
#pragma unroll
            for (int f = 0; f < 4; f++) acc[mt][nt][f] = 0.f;

    int nStages = K / BK;

#define STAGE(buf_, pa0, pa1, pb0, pb1)                                        \
    {                                                                          \
        uint32_t* Aw = (uint32_t*)&AsP[buf_][0][0];                            \
        uint32_t* Bw = (uint32_t*)&BsP[buf_][0][0];                            \
        uint4 _va[2] = {pa0, pa1};                                             \
        uint4 _vb[2] = {pb0, pb1};                                             \
        _Pragma("unroll")                                                      \
        for (int j = 0; j < 2; j++) {                                          \
            int r = r_st + j * 64;                                             \
            uint32_t* fa = (uint32_t*)&_va[j];                                 \
            uint32_t* fb = (uint32_t*)&_vb[j];                                 \
            _Pragma("unroll")                                                  \
            for (int q = 0; q < 4; q++) {                                      \
                int w = ((kp0 + q) * SM_STRIDE + r) * 2 + hh;                  \
                Aw[w] = fa[q];                                                 \
                Bw[w] = fb[q];                                                 \
            }                                                                  \
        }                                                                      \
    }

    const uint4 zero4 = make_uint4(0, 0, 0, 0);
    // prologue: stage 0
    {
        uint4 pa[2], pb[2];
#pragma unroll
        for (int j = 0; j < 2; j++) {
            int r = r_st + j * 64;
            int gr = m0 + r;
            pa[j] = (gr < M) ? *(const uint4*)&X[(size_t)gr * K + c4_st] : zero4;
            pb[j] = *(const uint4*)&V[(size_t)(n0 + r) * K + c4_st];
        }
        STAGE(0, pa[0], pa[1], pb[0], pb[1]);
    }
    __syncthreads();

    for (int s = 0; s < nStages; s++) {
        int buf = s & 1;
        uint4 pa[2], pb[2];
        bool hasNext = (s + 1) < nStages;
        if (hasNext) {
            int k0 = (s + 1) * BK;
#pragma unroll
            for (int j = 0; j < 2; j++) {
                int r = r_st + j * 64;
                int gr = m0 + r;
                pa[j] = (gr < M) ? *(const uint4*)&X[(size_t)gr * K + k0 + c4_st] : zero4;
                pb[j] = *(const uint4*)&V[(size_t)(n0 + r) * K + k0 + c4_st];
            }
        }

#pragma unroll
        for (int ks = 0; ks < BK; ks += 8) {
            int kp = tig + ((ks >> 3) << 2);
            uint32_t a[4][4];
#pragma unroll
            for (int mt = 0; mt < 4; mt++) {
                int m = warpM * 64 + mt * 16 + gid;
                uint2 vm  = AsP[buf][kp][m];
                uint2 vm8 = AsP[buf][kp][m + 8];
                a[mt][0] = vm.x;  a[mt][1] = vm8.x;
                a[mt][2] = vm.y;  a[mt][3] = vm8.y;
            }
            uint32_t b[4][2];
#pragma unroll
            for (int nt = 0; nt < 4; nt++) {
                int n = warpN * 32 + nt * 8 + gid;
                uint2 vn = BsP[buf][kp][n];
                b[nt][0] = vn.x;  b[nt][1] = vn.y;
            }
#pragma unroll
            for (int mt = 0; mt < 4; mt++)
#pragma unroll
                for (int nt = 0; nt < 4; nt++) {
                    asm volatile(
                        "mma.sync.aligned.m16n8k8.row.col.f32.tf32.tf32.f32 "
                        "{%0,%1,%2,%3}, {%4,%5,%6,%7}, {%8,%9}, {%0,%1,%2,%3};"
                        : "+f"(acc[mt][nt][0]), "+f"(acc[mt][nt][1]),
                          "+f"(acc[mt][nt][2]), "+f"(acc[mt][nt][3])
                        : "r"(a[mt][0]), "r"(a[mt][1]), "r"(a[mt][2]), "r"(a[mt][3]),
                          "r"(b[nt][0]), "r"(b[nt][1]));
                }
        }

        if (hasNext) {
            STAGE(buf ^ 1, pa[0], pa[1], pb[0], pb[1]);
        }
        __syncthreads();
    }
#undef STAGE

#pragma unroll
    for (int mt = 0; mt < 4; mt++) {
        int r0 = m0 + warpM * 64 + mt * 16 + gid;
        int r1 = r0 + 8;
#pragma unroll
        for (int nt = 0; nt < 4; nt++) {
            int col = n0 + warpN * 32 + nt * 8 + tig * 2;
            if (r0 < M)
                *(float2*)&g_T[(size_t)r0 * 512 + col] =
                    make_float2(acc[mt][nt][0], acc[mt][nt][1]);
            if (r1 < M)
                *(float2*)&g_T[(size_t)r1 * 512 + col] =
                    make_float2(acc[mt][nt][2], acc[mt][nt][3]);
        }
    }
}

// ---------------- aggregation + epilogue ------------------------------------
// acc = (deg+1)*(A[v]+b) + S[v] + WEA[v][c] + sum_{e->v} S[src_e]
// Intermediate layers write tf32 bits to g_z (next GEMM consumes them directly).
__global__ __launch_bounds__(256) void agg_kernel(const float* __restrict__ bias,
                           const float* __restrict__ gg,
                           const float* __restrict__ beta,
                           const float* __restrict__ rm,
                           const float* __restrict__ rv,
                           float* __restrict__ outp, int do_bn) {
    int v = blockIdx.x;
    int c = threadIdx.x;
    int lane = c & 31;

    int start = g_rowstart[v];
    int end   = start + g_deg[v];
    float a = g_T[(size_t)v * 512 + c];
    float s = g_T[(size_t)v * 512 + 256 + c];
    float dot = g_WEA[(size_t)v * FOUT + c];
    float acc0 = (float)(end - start + 1) * (a + bias[c]) + s + dot;
    float acc1 = 0.f, acc2 = 0.f, acc3 = 0.f;

    const float* Sbase = &g_T[256];
    for (int base = start; base < end; base += 32) {
        int m = end - base;
        if (m > 32) m = 32;
        int src = (lane < m) ? g_srcs[base + lane] : 0;
        int j = 0;
        for (; j + 4 <= m; j += 4) {
            int u0 = __shfl_sync(0xffffffffu, src, j + 0);
            int u1 = __shfl_sync(0xffffffffu, src, j + 1);
            int u2 = __shfl_sync(0xffffffffu, src, j + 2);
            int u3 = __shfl_sync(0xffffffffu, src, j + 3);
            float v0 = Sbase[(size_t)u0 * 512 + c];
            float v1 = Sbase[(size_t)u1 * 512 + c];
            float v2 = Sbase[(size_t)u2 * 512 + c];
            float v3 = Sbase[(size_t)u3 * 512 + c];
            acc0 += v0; acc1 += v1; acc2 += v2; acc3 += v3;
        }
        for (; j < m; j++) {
            int u = __shfl_sync(0xffffffffu, src, j);
            acc0 += Sbase[(size_t)u * 512 + c];
        }
    }
    float acc = (acc0 + acc1) + (acc2 + acc3);

    float r = fmaxf(acc, 0.f);
    if (do_bn) {
        r = (r - rm[c]) * rsqrtf(rv[c] + EPSV) * gg[c] + beta[c];
        r = fmaxf(r, 0.f);
    }
    if (outp) outp[(size_t)v * FOUT + c] = r;
    else      g_z[(size_t)v * FOUT + c] = f2tf32(r);
}

// ---------------- launch -----------------------------------------------------
extern "C" void kernel_launch(void* const* d_in, const int* in_sizes, int n_in,
                              void* d_out, int out_size) {
    const float* x   = (const float*)d_in[0];
    const int*   ei  = (const int*)d_in[1];
    const float* ea  = (const float*)d_in[2];
    const float* W0  = (const float*)d_in[3];
    const float* b0  = (const float*)d_in[4];
    const float* W1  = (const float*)d_in[5];
    const float* b1  = (const float*)d_in[6];
    const float* W2  = (const float*)d_in[7];
    const float* b2  = (const float*)d_in[8];
    const float* g0 = (const float*)d_in[9];
    const float* be0 = (const float*)d_in[10];
    const float* rm0 = (const float*)d_in[11];
    const float* rv0 = (const float*)d_in[12];
    const float* g1 = (const float*)d_in[13];
    const float* be1 = (const float*)d_in[14];
    const float* rm1 = (const float*)d_in[15];
    const float* rv1 = (const float*)d_in[16];
    float* outp = (float*)d_out;

    const int E = in_sizes[1] / 2;
    const int M = NNODES;

    detect_zero_kernel<<<(NNODES + 255) / 256, 256>>>(ei);
    hist_kernel<<<(E + 255) / 256, 256>>>(ei, E);
    alloc_kernel<<<(NNODES + 255) / 256, 256>>>();
    fill_kernel<<<(E + 255) / 256, 256>>>(ei, E);
    ea_kernel<<<(NNODES * 32 + 255) / 256, 256>>>(ea);
    xcvt_kernel<<<(NNODES * 128 / 4 + 255) / 256, 256>>>(x);
    {
        dim3 pg(132, 3);
        pack_all_kernel<<<pg, 256>>>(W0, W1, W2);
    }

    dim3 grid((M + 127) / 128, 512 / 128);
    // layer 0 (g_z currently holds tf32(x))
    wea_kernel<<<NNODES / 8, 256>>>(0);
    tgemm512<<<grid, 256>>>(0, M, 128);
    agg_kernel<<<M, 256>>>(b0, g0, be0, rm0, rv0, nullptr, 1);
    // layer 1
    wea_kernel<<<NNODES / 8, 256>>>(1);
    tgemm512<<<grid, 256>>>(1, M, 256);
    agg_kernel<<<M, 256>>>(b1, g1, be1, rm1, rv1, nullptr, 1);
    // layer 2
    wea_kernel<<<NNODES / 8, 256>>>(2);
    tgemm512<<<grid, 256>>>(2, M, 256);
    agg_kernel<<<M, 256>>>(b2, nullptr, nullptr, nullptr, nullptr, outp, 0);
}

// round 17
// speedup vs baseline: 3.6072x; 1.0385x over previous
#include <cuda_runtime.h>
#include <cuda_bf16.h>
#include <cstdint>

#define NNODES 20000
#define NEDGES 320000
#define FEA    16
#define FOUT   256
#define EPSV   1e-5f

// ---------------- scratch (static __device__ — no allocation allowed) -------
// All __device__ symbols are referenced ONLY from device code.
__device__ int      g_is64;
__device__ int      g_ctr;
__device__ int      g_deg[NNODES];
__device__ int      g_rowstart[NNODES];
__device__ int      g_cursor[NNODES];
__device__ int      g_srcs[NEDGES];
__device__ int      g_eids[NEDGES];
__device__ float    g_EA[NNODES * FEA];        // per-node summed edge_attr (+0; +1 applied in agg)
__device__ float    g_T[NNODES * 512];         // [A | S] per node (fp32)
__device__ uint32_t g_z[NNODES * FOUT];        // tf32 bits: x (layer 0) / activations
__device__ uint32_t g_V[3 * 512 * 256];        // packed [Wd; Ws] (tf32 bits), per layer
__device__ float    g_WeT[3 * FEA * FOUT];     // [l][k][c]  (coalesced in c)

__device__ __forceinline__ int edge_val(const int* ei, int E, int which, int e) {
    if (g_is64) return ei[2 * (which * E + e)];
    return ei[which * E + e];
}

__device__ __forceinline__ uint32_t f2tf32(float v) {
    uint32_t t;
    asm("cvt.rna.tf32.f32 %0, %1;" : "=r"(t) : "f"(v));
    return t;
}

// ---------------- dtype detect + init ---------------------------------------
__global__ void detect_zero_kernel(const int* __restrict__ ei) {
    int i = blockIdx.x * blockDim.x + threadIdx.x;
    if (i < NNODES) g_deg[i] = 0;
    if (blockIdx.x == 0 && threadIdx.x == 0) {
        int all0 = 1;
        for (int k = 1; k < 128; k += 2)
            if (ei[k] != 0) { all0 = 0; break; }
        g_is64 = all0;
        g_ctr = 0;
    }
}

__global__ void hist_kernel(const int* __restrict__ ei, int E) {
    int e = blockIdx.x * blockDim.x + threadIdx.x;
    if (e < E) {
        int d = edge_val(ei, E, 1, e);
        atomicAdd(&g_deg[d], 1);
    }
}

// Parallel bucket allocation: block scan + one atomicAdd per block.
__global__ void alloc_kernel() {
    int tid = threadIdx.x;
    int i = blockIdx.x * 256 + tid;
    int lane = tid & 31, wid = tid >> 5;
    int d = (i < NNODES) ? g_deg[i] : 0;
    int v = d;
#pragma unroll
    for (int o = 1; o < 32; o <<= 1) {
        int t = __shfl_up_sync(0xffffffffu, v, o);
        if (lane >= o) v += t;
    }
    __shared__ int wsum[8];
    __shared__ int blockbase;
    if (lane == 31) wsum[wid] = v;
    __syncthreads();
    if (wid == 0) {
        int s = (lane < 8) ? wsum[lane] : 0;
#pragma unroll
        for (int o = 1; o < 8; o <<= 1) {
            int t = __shfl_up_sync(0xffffffffu, s, o);
            if (lane >= o) s += t;
        }
        if (lane < 8) wsum[lane] = s;
        if (lane == 7) blockbase = atomicAdd(&g_ctr, s);
    }
    __syncthreads();
    int excl = v - d + (wid ? wsum[wid - 1] : 0);
    if (i < NNODES) {
        int st = blockbase + excl;
        g_rowstart[i] = st;
        g_cursor[i] = st;
    }
}

__global__ void fill_kernel(const int* __restrict__ ei, int E) {
    int e = blockIdx.x * blockDim.x + threadIdx.x;
    if (e < E) {
        int s = edge_val(ei, E, 0, e);
        int d = edge_val(ei, E, 1, e);
        int pos = atomicAdd(&g_cursor[d], 1);
        g_srcs[pos] = s;
        g_eids[pos] = e;
    }
}

// EA[v][k] = sum over incoming edges of ea[e][k]. One warp per node.
__global__ void ea_kernel(const float* __restrict__ ea) {
    int warp = (blockIdx.x * blockDim.x + threadIdx.x) >> 5;
    if (warp >= NNODES) return;
    int lane = threadIdx.x & 31;
    int j = lane >> 4, k = lane & 15;
    int start = g_rowstart[warp];
    int end   = start + g_deg[warp];
    float acc = 0.f;
    for (int b = start + j; b < end; b += 2) {
        int e = g_eids[b];
        acc += ea[e * FEA + k];
    }
    acc += __shfl_down_sync(0xffffffffu, acc, 16);
    if (lane < 16) g_EA[warp * FEA + k] = acc;
}

// Convert x to tf32 bits into g_z (layer-0 GEMM input; later overwritten by agg).
__global__ void xcvt_kernel(const float* __restrict__ x) {
    int i = blockIdx.x * blockDim.x + threadIdx.x;   // float4 index
    if (i < NNODES * 128 / 4) {
        float4 v = *(const float4*)&x[i * 4];
        uint4 u;
        u.x = f2tf32(v.x); u.y = f2tf32(v.y);
        u.z = f2tf32(v.z); u.w = f2tf32(v.w);
        *(uint4*)&g_z[i * 4] = u;
    }
}

// ---------------- all-layer weight pack (tf32 bits) --------------------------
__global__ void pack_all_kernel(const float* __restrict__ W0,
                                const float* __restrict__ W1,
                                const float* __restrict__ W2) {
    int l = blockIdx.y;
    const float* W = (l == 0) ? W0 : (l == 1) ? W1 : W2;
    int K = (l == 0) ? 128 : 256;
    int ldw = 2 * K + FEA;
    int total = 512 * K + FOUT * FEA;
    uint32_t* V = g_V + l * (512 * 256);
    float* WeT = g_WeT + l * (FEA * FOUT);
    for (int idx = blockIdx.x * blockDim.x + threadIdx.x; idx < total;
         idx += gridDim.x * blockDim.x) {
        if (idx < 512 * K) {
            int j = idx / K, k = idx - j * K;
            int row = j & 255;
            int off = (j >= 256) ? K : 0;
            V[idx] = f2tf32(W[row * ldw + off + k]);
        } else {
            int i2 = idx - 512 * K;
            int c = i2 >> 4, k = i2 & 15;
            WeT[k * FOUT + c] = W[c * ldw + 2 * K + k];
        }
    }
}

// ---------------- TF32 tensor-core GEMM: T[M x 512] = g_z[M x K] * V_l^T -----
#define SM_STRIDE 132
__global__ __launch_bounds__(256, 2) void tgemm512(int layer, int M, int K) {
    const uint32_t* __restrict__ X = g_z;
    const uint32_t* __restrict__ V = g_V + layer * (512 * 256);
    constexpr int BM = 128, BK = 16;
    __shared__ uint2 AsP[2][8][SM_STRIDE];
    __shared__ uint2 BsP[2][8][SM_STRIDE];
    int tid  = threadIdx.x;
    int lane = tid & 31;
    int warp = tid >> 5;
    int gid  = lane >> 2;
    int tig  = lane & 3;
    int warpM = warp >> 2;
    int warpN = warp & 3;
    int m0 = blockIdx.x * BM;
    int n0 = blockIdx.y * BM;

    int r_st  = tid >> 2;
    int c4_st = (tid & 3) * 4;
    int kp0   = (c4_st & 8) >> 1;
    int hh    = (c4_st >> 2) & 1;

    float acc[4][4][4];
#pragma unroll
    for (int mt = 0; mt < 4; mt++)
#pragma unroll
        for (int nt = 0; nt < 4; nt++)
#pragma unroll
            for (int f = 0; f < 4; f++) acc[mt][nt][f] = 0.f;

    int nStages = K / BK;

#define STAGE(buf_, pa0, pa1, pb0, pb1)                                        \
    {                                                                          \
        uint32_t* Aw = (uint32_t*)&AsP[buf_][0][0];                            \
        uint32_t* Bw = (uint32_t*)&BsP[buf_][0][0];                            \
        uint4 _va[2] = {pa0, pa1};                                             \
        uint4 _vb[2] = {pb0, pb1};                                             \
        _Pragma("unroll")                                                      \
        for (int j = 0; j < 2; j++) {                                          \
            int r = r_st + j * 64;                                             \
            uint32_t* fa = (uint32_t*)&_va[j];                                 \
            uint32_t* fb = (uint32_t*)&_vb[j];                                 \
            _Pragma("unroll")                                                  \
            for (int q = 0; q < 4; q++) {                                      \
                int w = ((kp0 + q) * SM_STRIDE + r) * 2 + hh;                  \
                Aw[w] = fa[q];                                                 \
                Bw[w] = fb[q];                                                 \
            }                                                                  \
        }                                                                      \
    }

    const uint4 zero4 = make_uint4(0, 0, 0, 0);
    // prologue: stage 0
    {
        uint4 pa[2], pb[2];
#pragma unroll
        for (int j = 0; j < 2; j++) {
            int r = r_st + j * 64;
            int gr = m0 + r;
            pa[j] = (gr < M) ? *(const uint4*)&X[(size_t)gr * K + c4_st] : zero4;
            pb[j] = *(const uint4*)&V[(size_t)(n0 + r) * K + c4_st];
        }
        STAGE(0, pa[0], pa[1], pb[0], pb[1]);
    }
    __syncthreads();

    for (int s = 0; s < nStages; s++) {
        int buf = s & 1;
        uint4 pa[2], pb[2];
        bool hasNext = (s + 1) < nStages;
        if (hasNext) {
            int k0 = (s + 1) * BK;
#pragma unroll
            for (int j = 0; j < 2; j++) {
                int r = r_st + j * 64;
                int gr = m0 + r;
                pa[j] = (gr < M) ? *(const uint4*)&X[(size_t)gr * K + k0 + c4_st] : zero4;
                pb[j] = *(const uint4*)&V[(size_t)(n0 + r) * K + k0 + c4_st];
            }
        }

#pragma unroll
        for (int ks = 0; ks < BK; ks += 8) {
            int kp = tig + ((ks >> 3) << 2);
            uint32_t a[4][4];
#pragma unroll
            for (int mt = 0; mt < 4; mt++) {
                int m = warpM * 64 + mt * 16 + gid;
                uint2 vm  = AsP[buf][kp][m];
                uint2 vm8 = AsP[buf][kp][m + 8];
                a[mt][0] = vm.x;  a[mt][1] = vm8.x;
                a[mt][2] = vm.y;  a[mt][3] = vm8.y;
            }
            uint32_t b[4][2];
#pragma unroll
            for (int nt = 0; nt < 4; nt++) {
                int n = warpN * 32 + nt * 8 + gid;
                uint2 vn = BsP[buf][kp][n];
                b[nt][0] = vn.x;  b[nt][1] = vn.y;
            }
#pragma unroll
            for (int mt = 0; mt < 4; mt++)
#pragma unroll
                for (int nt = 0; nt < 4; nt++) {
                    asm volatile(
                        "mma.sync.aligned.m16n8k8.row.col.f32.tf32.tf32.f32 "
                        "{%0,%1,%2,%3}, {%4,%5,%6,%7}, {%8,%9}, {%0,%1,%2,%3};"
                        : "+f"(acc[mt][nt][0]), "+f"(acc[mt][nt][1]),
                          "+f"(acc[mt][nt][2]), "+f"(acc[mt][nt][3])
                        : "r"(a[mt][0]), "r"(a[mt][1]), "r"(a[mt][2]), "r"(a[mt][3]),
                          "r"(b[nt][0]), "r"(b[nt][1]));
                }
        }

        if (hasNext) {
            STAGE(buf ^ 1, pa[0], pa[1], pb[0], pb[1]);
        }
        __syncthreads();
    }
#undef STAGE

#pragma unroll
    for (int mt = 0; mt < 4; mt++) {
        int r0 = m0 + warpM * 64 + mt * 16 + gid;
        int r1 = r0 + 8;
#pragma unroll
        for (int nt = 0; nt < 4; nt++) {
            int col = n0 + warpN * 32 + nt * 8 + tig * 2;
            if (r0 < M)
                *(float2*)&g_T[(size_t)r0 * 512 + col] =
                    make_float2(acc[mt][nt][0], acc[mt][nt][1]);
            if (r1 < M)
                *(float2*)&g_T[(size_t)r1 * 512 + col] =
                    make_float2(acc[mt][nt][2], acc[mt][nt][3]);
        }
    }
}

// ---------------- aggregation + epilogue ------------------------------------
// acc = (deg+1)*(A[v]+b) + S[v] + dot(WeT_l[:,c], EA[v]+1) + sum_{e->v} S[src_e]
// WeT is [k][c] — coalesced per-channel loads, L1-resident (16 KB).
__global__ __launch_bounds__(256) void agg_kernel(int layer,
                           const float* __restrict__ bias,
                           const float* __restrict__ gg,
                           const float* __restrict__ beta,
                           const float* __restrict__ rm,
                           const float* __restrict__ rv,
                           float* __restrict__ outp, int do_bn) {
    int v = blockIdx.x;
    int c = threadIdx.x;
    int lane = c & 31;

    __shared__ float sEA[FEA];
    if (c < FEA) sEA[c] = g_EA[v * FEA + c] + 1.0f;
    __syncthreads();

    const float* WeT = g_WeT + layer * (FEA * FOUT);
    float dot = 0.f;
#pragma unroll
    for (int k = 0; k < FEA; k++) dot = fmaf(WeT[k * FOUT + c], sEA[k], dot);

    int start = g_rowstart[v];
    int end   = start + g_deg[v];
    float a = g_T[(size_t)v * 512 + c];
    float s = g_T[(size_t)v * 512 + 256 + c];
    float acc0 = (float)(end - start + 1) * (a + bias[c]) + s + dot;
    float acc1 = 0.f, acc2 = 0.f, acc3 = 0.f;

    const float* Sbase = &g_T[256];
    for (int base = start; base < end; base += 32) {
        int m = end - base;
        if (m > 32) m = 32;
        int src = (lane < m) ? g_srcs[base + lane] : 0;
        int j = 0;
        for (; j + 4 <= m; j += 4) {
            int u0 = __shfl_sync(0xffffffffu, src, j + 0);
            int u1 = __shfl_sync(0xffffffffu, src, j + 1);
            int u2 = __shfl_sync(0xffffffffu, src, j + 2);
            int u3 = __shfl_sync(0xffffffffu, src, j + 3);
            float v0 = Sbase[(size_t)u0 * 512 + c];
            float v1 = Sbase[(size_t)u1 * 512 + c];
            float v2 = Sbase[(size_t)u2 * 512 + c];
            float v3 = Sbase[(size_t)u3 * 512 + c];
            acc0 += v0; acc1 += v1; acc2 += v2; acc3 += v3;
        }
        for (; j < m; j++) {
            int u = __shfl_sync(0xffffffffu, src, j);
            acc0 += Sbase[(size_t)u * 512 + c];
        }
    }
    float acc = (acc0 + acc1) + (acc2 + acc3);

    float r = fmaxf(acc, 0.f);
    if (do_bn) {
        r = (r - rm[c]) * rsqrtf(rv[c] + EPSV) * gg[c] + beta[c];
        r = fmaxf(r, 0.f);
    }
    if (outp) outp[(size_t)v * FOUT + c] = r;
    else      g_z[(size_t)v * FOUT + c] = f2tf32(r);
}

// ---------------- launch -----------------------------------------------------
extern "C" void kernel_launch(void* const* d_in, const int* in_sizes, int n_in,
                              void* d_out, int out_size) {
    const float* x   = (const float*)d_in[0];
    const int*   ei  = (const int*)d_in[1];
    const float* ea  = (const float*)d_in[2];
    const float* W0  = (const float*)d_in[3];
    const float* b0  = (const float*)d_in[4];
    const float* W1  = (const float*)d_in[5];
    const float* b1  = (const float*)d_in[6];
    const float* W2  = (const float*)d_in[7];
    const float* b2  = (const float*)d_in[8];
    const float* g0 = (const float*)d_in[9];
    const float* be0 = (const float*)d_in[10];
    const float* rm0 = (const float*)d_in[11];
    const float* rv0 = (const float*)d_in[12];
    const float* g1 = (const float*)d_in[13];
    const float* be1 = (const float*)d_in[14];
    const float* rm1 = (const float*)d_in[15];
    const float* rv1 = (const float*)d_in[16];
    float* outp = (float*)d_out;

    const int E = in_sizes[1] / 2;
    const int M = NNODES;

    detect_zero_kernel<<<(NNODES + 255) / 256, 256>>>(ei);
    hist_kernel<<<(E + 255) / 256, 256>>>(ei, E);
    alloc_kernel<<<(NNODES + 255) / 256, 256>>>();
    fill_kernel<<<(E + 255) / 256, 256>>>(ei, E);
    ea_kernel<<<(NNODES * 32 + 255) / 256, 256>>>(ea);
    xcvt_kernel<<<(NNODES * 128 / 4 + 255) / 256, 256>>>(x);
    {
        dim3 pg(132, 3);
        pack_all_kernel<<<pg, 256>>>(W0, W1, W2);
    }

    dim3 grid((M + 127) / 128, 512 / 128);
    // layer 0 (g_z currently holds tf32(x))
    tgemm512<<<grid, 256>>>(0, M, 128);
    agg_kernel<<<M, 256>>>(0, b0, g0, be0, rm0, rv0, nullptr, 1);
    // layer 1
    tgemm512<<<grid, 256>>>(1, M, 256);
    agg_kernel<<<M, 256>>>(1, b1, g1, be1, rm1, rv1, nullptr, 1);
    // layer 2
    tgemm512<<<grid, 256>>>(2, M, 256);
    agg_kernel<<<M, 256>>>(2, b2, nullptr, nullptr, nullptr, nullptr, outp, 0);
}